// round 11
// baseline (speedup 1.0000x reference)
#include <cuda_runtime.h>
#include <cuda_bf16.h>
#include <math.h>
#include <stdint.h>

// ---------------------------------------------------------------- constants
#define B_   64
#define S_   1000
#define D_   512          // N of the GEMM
#define K2_  1024         // K of the GEMM
#define M_   (B_ * S_)    // 64000

#define TMM  64           // CTA M tile (small -> 2 CTAs/SM)
#define KC   64           // K chunk (64 bf16 = 128B swizzled rows)
#define NCH  16           // K2_/KC
#define NPASS 4           // N passes of 128 cols
#define NT   256          // threads per CTA (8 warps = 2M x 4N)

// ------------------------------------------------------------- device scratch
__device__ float g_hW[B_ * D_];
__device__ float g_logits[M_];
// W_bot pre-split (hi/lo bf16), transposed [n][k], SW128-swizzled per chunk
__device__ __align__(16) uint8_t g_wprep_hi[NCH * D_ * 128];
__device__ __align__(16) uint8_t g_wprep_lo[NCH * D_ * 128];
// enc pre-split to bf16 hi/lo, row-major [M_][K2_] (2KB rows), NOT swizzled
__device__ __align__(16) uint8_t g_enc_hi[(size_t)M_ * K2_ * 2];
__device__ __align__(16) uint8_t g_enc_lo[(size_t)M_ * K2_ * 2];

// ---------------------------------------------------------------- smem layout
// A: [stage][plane][64 rows][128B]  -> 4 x 8KB  = 32KB
// B: [stage][plane][128 rows][128B] -> 4 x 16KB = 64KB
#define SA(st, pl)  ((st) * 16384 + (pl) * 8192)
#define SB(st, pl)  (32768 + (st) * 32768 + (pl) * 16384)
#define SM_SV   98304       // 512 f32
#define SM_HW0  100352      // 512 f32
#define SM_HW1  102400      // 512 f32
#define SM_RS   104448      // 64 f32
#define SM_TOTAL 104704

// ---------------------------------------------------------------- helpers
__device__ __forceinline__ uint32_t smem_u32(const void* p) {
    uint32_t a;
    asm("{ .reg .u64 t; cvta.to.shared.u64 t, %1; cvt.u32.u64 %0, t; }" : "=r"(a) : "l"(p));
    return a;
}
__host__ __device__ __forceinline__ uint32_t swz128(uint32_t off) {
    return off ^ ((off >> 3) & 0x70);
}
#define LDSM4(R, A)                                                             \
    asm volatile("ldmatrix.sync.aligned.m8n8.x4.shared.b16 {%0,%1,%2,%3}, [%4];" \
        : "=r"((R)[0]), "=r"((R)[1]), "=r"((R)[2]), "=r"((R)[3]) : "r"(A))
__device__ __forceinline__ void mma_bf16(float* c, const uint32_t* a, const uint32_t* b) {
    asm volatile("mma.sync.aligned.m16n8k16.row.col.f32.bf16.bf16.f32 "
        "{%0,%1,%2,%3},{%4,%5,%6,%7},{%8,%9},{%0,%1,%2,%3};"
        : "+f"(c[0]), "+f"(c[1]), "+f"(c[2]), "+f"(c[3])
        : "r"(a[0]), "r"(a[1]), "r"(a[2]), "r"(a[3]), "r"(b[0]), "r"(b[1]));
}
#define CP16(dst, src) \
    asm volatile("cp.async.cg.shared.global [%0], [%1], 16;" :: "r"(dst), "l"(src) : "memory")
#define CP_COMMIT() asm volatile("cp.async.commit_group;" ::: "memory")
#define CP_WAIT0()  asm volatile("cp.async.wait_group 0;" ::: "memory")

// ---------------------------------------------------------------------------
// FUSED prep kernel: conv_enc [0,8000) | hw [8000,8256) | conv_w [8256,8320)
// All three are independent; one launch fills the machine concurrently.
// block = 512 threads.
// ---------------------------------------------------------------------------
__global__ __launch_bounds__(512)
void prep_kernel(const float* __restrict__ enc,
                 const float* __restrict__ hidden,
                 const float* __restrict__ attn_w,
                 const float* __restrict__ attn_b) {
    const int bx = blockIdx.x;
    const int tid = threadIdx.x;

    if (bx < 8000) {
        // ---- conv_enc: 8 rows per block --------------------------------
        const int r = bx * 8 + (tid >> 6);
        const int c = (tid & 63) * 16;
        const float4* p = reinterpret_cast<const float4*>(enc + (size_t)r * K2_ + c);
        uint2* dh = reinterpret_cast<uint2*>(g_enc_hi + (size_t)r * (K2_ * 2) + c * 2);
        uint2* dl = reinterpret_cast<uint2*>(g_enc_lo + (size_t)r * (K2_ * 2) + c * 2);
        #pragma unroll
        for (int j = 0; j < 4; j++) {
            float4 f = p[j];
            __nv_bfloat16 h0 = __float2bfloat16(f.x);
            __nv_bfloat16 h1 = __float2bfloat16(f.y);
            __nv_bfloat16 h2 = __float2bfloat16(f.z);
            __nv_bfloat16 h3 = __float2bfloat16(f.w);
            __nv_bfloat16 l0 = __float2bfloat16(f.x - __bfloat162float(h0));
            __nv_bfloat16 l1 = __float2bfloat16(f.y - __bfloat162float(h1));
            __nv_bfloat16 l2 = __float2bfloat16(f.z - __bfloat162float(h2));
            __nv_bfloat16 l3 = __float2bfloat16(f.w - __bfloat162float(h3));
            __nv_bfloat162 hp0 = __halves2bfloat162(h0, h1);
            __nv_bfloat162 hp1 = __halves2bfloat162(h2, h3);
            __nv_bfloat162 lp0 = __halves2bfloat162(l0, l1);
            __nv_bfloat162 lp1 = __halves2bfloat162(l2, l3);
            dh[j] = make_uint2(*reinterpret_cast<uint32_t*>(&hp0),
                               *reinterpret_cast<uint32_t*>(&hp1));
            dl[j] = make_uint2(*reinterpret_cast<uint32_t*>(&lp0),
                               *reinterpret_cast<uint32_t*>(&lp1));
        }
    } else if (bx < 8256) {
        // ---- hW: 512 thr = 128 n-cols x 4 k-slices ----------------------
        __shared__ float sh[D_];
        __shared__ float part[3][128];
        const int bi = bx - 8000;
        const int b  = bi >> 2;
        const int ng = bi & 3;
        const int nl = tid & 127;
        const int ks = tid >> 7;
        const int n  = ng * 128 + nl;
        for (int i = tid; i < D_; i += 512) sh[i] = hidden[b * D_ + i];
        __syncthreads();
        const int k0 = ks * 128;
        float a0 = 0.f, a1 = 0.f, a2 = 0.f, a3 = 0.f;
        #pragma unroll 8
        for (int k = k0; k < k0 + 128; k += 4) {
            a0 += sh[k + 0] * attn_w[(k + 0) * D_ + n];
            a1 += sh[k + 1] * attn_w[(k + 1) * D_ + n];
            a2 += sh[k + 2] * attn_w[(k + 2) * D_ + n];
            a3 += sh[k + 3] * attn_w[(k + 3) * D_ + n];
        }
        float acc = (a0 + a1) + (a2 + a3);
        if (ks) part[ks - 1][nl] = acc;
        __syncthreads();
        if (ks == 0)
            g_hW[b * D_ + n] = attn_b[n] + acc + part[0][nl] + part[1][nl] + part[2][nl];
    } else {
        // ---- conv_w: split + transpose + swizzle W_bot ------------------
        const int bi = bx - 8256;
        const int chunk = bi >> 2;
        const int kg0 = (bi & 3) * 16;
        const int n = tid;
        uint8_t* dh = g_wprep_hi + chunk * (D_ * 128);
        uint8_t* dl = g_wprep_lo + chunk * (D_ * 128);
        for (int kk = kg0; kk < kg0 + 16; kk++) {
            const int kg = D_ + chunk * KC + kk;
            float w = attn_w[(size_t)kg * D_ + n];
            __nv_bfloat16 hi = __float2bfloat16(w);
            __nv_bfloat16 lo = __float2bfloat16(w - __bfloat162float(hi));
            uint32_t sw = swz128((uint32_t)(n * 128 + kk * 2));
            *reinterpret_cast<uint16_t*>(dh + sw) = *reinterpret_cast<uint16_t*>(&hi);
            *reinterpret_cast<uint16_t*>(dl + sw) = *reinterpret_cast<uint16_t*>(&lo);
        }
    }
}

// ---------------------------------------------------------------------------
// Main HMMA GEMM + tanh + v-dot.  grid(1000), block(256), 2 CTAs/SM.
// 8 warps = 2M(32 rows) x 4N(32 cols); ONE __syncthreads per chunk.
// ---------------------------------------------------------------------------
__global__ __launch_bounds__(NT, 2)
void gemm_kernel(const float* __restrict__ v) {
    extern __shared__ __align__(1024) uint8_t smem[];
    const uint32_t sb = smem_u32(smem);
    const int tid  = threadIdx.x;
    const int wid  = tid >> 5;
    const int lane = tid & 31;
    const int wm   = wid >> 2;          // 0..1 (32 M rows each)
    const int wn   = wid & 3;           // 0..3 (32 N cols each)
    const int m0   = blockIdx.x * TMM;

    float* svp = reinterpret_cast<float*>(smem + SM_SV);
    float* hw0 = reinterpret_cast<float*>(smem + SM_HW0);
    float* hw1 = reinterpret_cast<float*>(smem + SM_HW1);
    float* rsm = reinterpret_cast<float*>(smem + SM_RS);

    const int b0 = m0 / S_;
    const int b1 = (m0 + TMM - 1) / S_;
    const int thr = (b0 + 1) * S_ - m0;   // rows >= thr belong to b1
    for (int i = tid; i < D_; i += NT) {
        svp[i] = v[i];
        hw0[i] = g_hW[b0 * D_ + i];
        hw1[i] = g_hW[b1 * D_ + i];
    }
    if (tid < TMM) rsm[tid] = 0.f;

    // ---- per-lane ldmatrix address components ------------------------------
    const int a_r16 = lane & 15;
    const uint32_t a_kext = (lane >> 4) << 4;
    uint32_t aoff[2], aswz[2];
    #pragma unroll
    for (int ms = 0; ms < 2; ms++) {
        int r = wm * 32 + ms * 16 + a_r16;
        aoff[ms] = (uint32_t)r * 128;
        aswz[ms] = (uint32_t)(r & 7) << 4;
    }
    const int b_r16 = (lane & 7) | ((lane & 16) >> 1);
    const uint32_t b_kext = (lane & 8) << 1;
    uint32_t boff[2], bsw[2];
    #pragma unroll
    for (int np = 0; np < 2; np++) {
        int r = wn * 32 + np * 16 + b_r16;
        boff[np] = (uint32_t)r * 128;
        bsw[np]  = (uint32_t)(r & 7) << 4;
    }

    // ---- cp.async loader ----------------------------------------------------
    auto loadAB = [&](int pass, int chunk, int st) {
        #pragma unroll
        for (int j = 0; j < 2; j++) {
            uint32_t p = (uint32_t)tid + j * NT;
            uint32_t row = p >> 3, c16 = p & 7;
            uint32_t dsto = row * 128 + ((c16 << 4) ^ ((row & 7) << 4));
            size_t   srco = (size_t)(m0 + row) * (K2_ * 2) + chunk * 128 + (c16 << 4);
            CP16(sb + SA(st, 0) + dsto, g_enc_hi + srco);
            CP16(sb + SA(st, 1) + dsto, g_enc_lo + srco);
        }
        const uint8_t* gh = g_wprep_hi + chunk * (D_ * 128) + pass * (128 * 128);
        const uint8_t* gl = g_wprep_lo + chunk * (D_ * 128) + pass * (128 * 128);
        #pragma unroll
        for (int j = 0; j < 4; j++) {
            uint32_t idx = (uint32_t)(tid + j * NT) * 16;   // straight copy keeps swizzle
            CP16(sb + SB(st, 0) + idx, gh + idx);
            CP16(sb + SB(st, 1) + idx, gl + idx);
        }
        CP_COMMIT();
    };

    float acc[2][4][4];   // [ms][np*2+half][4]

    auto compute = [&](int st) {
        const uint32_t baseAh = sb + SA(st, 0);
        const uint32_t baseAl = sb + SA(st, 1);
        const uint32_t baseBh = sb + SB(st, 0);
        const uint32_t baseBl = sb + SB(st, 1);
        #pragma unroll
        for (int k16 = 0; k16 < 4; k16++) {
            const uint32_t ka = (uint32_t)(k16 * 32) + a_kext;
            const uint32_t kb = (uint32_t)(k16 * 32) + b_kext;
            uint32_t ah[2][4], al[2][4];
            #pragma unroll
            for (int ms = 0; ms < 2; ms++) {
                uint32_t o = aoff[ms] + (ka ^ aswz[ms]);
                LDSM4(ah[ms], baseAh + o);
                LDSM4(al[ms], baseAl + o);
            }
            #pragma unroll
            for (int np = 0; np < 2; np++) {
                const uint32_t o = boff[np] + (kb ^ bsw[np]);
                uint32_t bh[4], bl[4];
                LDSM4(bh, baseBh + o);
                #pragma unroll
                for (int ms = 0; ms < 2; ms++) {
                    mma_bf16(acc[ms][np * 2 + 0], ah[ms], bh + 0);
                    mma_bf16(acc[ms][np * 2 + 1], ah[ms], bh + 2);
                    mma_bf16(acc[ms][np * 2 + 0], al[ms], bh + 0);
                    mma_bf16(acc[ms][np * 2 + 1], al[ms], bh + 2);
                }
                LDSM4(bl, baseBl + o);
                #pragma unroll
                for (int ms = 0; ms < 2; ms++) {
                    mma_bf16(acc[ms][np * 2 + 0], ah[ms], bl + 0);
                    mma_bf16(acc[ms][np * 2 + 1], ah[ms], bl + 2);
                }
            }
        }
    };

    const int gid = lane >> 2;
    const int tig = lane & 3;

    // ======================= four N-passes (128 cols each) ==================
    #pragma unroll 1
    for (int pass = 0; pass < NPASS; pass++) {
        #pragma unroll
        for (int ms = 0; ms < 2; ms++)
            #pragma unroll
            for (int f = 0; f < 4; f++)
                #pragma unroll
                for (int c = 0; c < 4; c++) acc[ms][f][c] = 0.f;

        // pass prologue: stage 0 was last read two chunks before the previous
        // epilogue -> barrier protects it from the new cp.async writes.
        __syncthreads();
        loadAB(pass, 0, 0);

        // ONE sync per chunk:
        //   CP_WAIT0 -> chunk i data landed (this thread's pending group)
        //   sync     -> data visible to all; all warps done reading stage s^1
        //   loadAB(i+1 -> s^1)  (safe: last readers were compute(i-1))
        //   compute(i on stage s)
        #pragma unroll 1
        for (int i = 0; i < NCH; i++) {
            const int s = i & 1;
            CP_WAIT0();
            __syncthreads();
            if (i + 1 < NCH) loadAB(pass, i + 1, s ^ 1);
            compute(s);
        }

        // epilogue: x = acc + hW, rowsum += v * tanh(x)
        #pragma unroll
        for (int ms = 0; ms < 2; ms++) {
            #pragma unroll
            for (int ch = 0; ch < 2; ch++) {
                const int r = wm * 32 + ms * 16 + ch * 8 + gid;
                const float* hwrow = (r >= thr) ? hw1 : hw0;
                float rs = 0.f;
                #pragma unroll
                for (int f = 0; f < 4; f++) {
                    const int n = pass * 128 + wn * 32 + f * 8 + tig * 2;
                    float x0 = acc[ms][f][ch * 2 + 0] + hwrow[n];
                    float x1 = acc[ms][f][ch * 2 + 1] + hwrow[n + 1];
                    rs += svp[n] * tanhf(x0) + svp[n + 1] * tanhf(x1);
                }
                rs += __shfl_xor_sync(0xffffffffu, rs, 1);
                rs += __shfl_xor_sync(0xffffffffu, rs, 2);
                if (tig == 0) atomicAdd(&rsm[r], rs);
            }
        }
    }

    __syncthreads();
    if (tid < TMM) g_logits[m0 + tid] = rsm[tid];
}

// ---------------------------------------------------------------------------
// softmax over S per batch. grid(64), block(256)
// ---------------------------------------------------------------------------
__global__ void softmax_kernel(float* __restrict__ out) {
    __shared__ float red[256];
    const int b = blockIdx.x;
    const int t = threadIdx.x;
    const float* row = g_logits + b * S_;
    float* orow = out + b * S_;

    float mx = -INFINITY;
    for (int i = t; i < S_; i += 256) mx = fmaxf(mx, row[i]);
    red[t] = mx;
    __syncthreads();
    for (int off = 128; off > 0; off >>= 1) {
        if (t < off) red[t] = fmaxf(red[t], red[t + off]);
        __syncthreads();
    }
    mx = red[0];
    __syncthreads();

    float sum = 0.f;
    for (int i = t; i < S_; i += 256) {
        float e = expf(row[i] - mx);
        orow[i] = e;
        sum += e;
    }
    red[t] = sum;
    __syncthreads();
    for (int off = 128; off > 0; off >>= 1) {
        if (t < off) red[t] += red[t + off];
        __syncthreads();
    }
    const float inv = 1.f / red[0];
    __syncthreads();
    for (int i = t; i < S_; i += 256) orow[i] *= inv;
}

// ---------------------------------------------------------------------------
extern "C" void kernel_launch(void* const* d_in, const int* in_sizes, int n_in,
                              void* d_out, int out_size) {
    const float* hidden = (const float*)d_in[0];   // [64, 512]
    const float* enc    = (const float*)d_in[1];   // [64, 1000, 1024]
    const float* attn_w = (const float*)d_in[2];   // [1536, 512]
    const float* attn_b = (const float*)d_in[3];   // [512]
    const float* v      = (const float*)d_in[4];   // [512]
    float* out = (float*)d_out;                    // [64, 1000]

    cudaFuncSetAttribute(gemm_kernel,
                         cudaFuncAttributeMaxDynamicSharedMemorySize, SM_TOTAL);

    prep_kernel<<<8320, 512>>>(enc, hidden, attn_w, attn_b);
    gemm_kernel<<<M_ / TMM, NT, SM_TOTAL>>>(v);
    softmax_kernel<<<B_, 256>>>(out);
}

// round 12
// speedup vs baseline: 1.0108x; 1.0108x over previous
#include <cuda_runtime.h>
#include <cuda_bf16.h>
#include <math.h>
#include <stdint.h>

// ---------------------------------------------------------------- constants
#define B_   64
#define S_   1000
#define D_   512          // N of the GEMM
#define K2_  1024         // K of the GEMM
#define M_   (B_ * S_)    // 64000

#define TMM  64           // CTA M tile (small -> 2 CTAs/SM)
#define KC   64           // K chunk (64 bf16 = 128B swizzled rows)
#define NCH  16           // K2_/KC
#define NT   256          // threads per CTA (8 warps = 2M x 4N)
#define PPC  2            // N-passes per CTA (split-N: 2 CTAs per m-tile)

// ------------------------------------------------------------- device scratch
__device__ float g_hW[B_ * D_];
__device__ float g_logits[M_];
// W_bot pre-split (hi/lo bf16), transposed [n][k], SW128-swizzled per chunk
__device__ __align__(16) uint8_t g_wprep_hi[NCH * D_ * 128];
__device__ __align__(16) uint8_t g_wprep_lo[NCH * D_ * 128];
// enc pre-split to bf16 hi/lo, row-major [M_][K2_] (2KB rows), NOT swizzled
__device__ __align__(16) uint8_t g_enc_hi[(size_t)M_ * K2_ * 2];
__device__ __align__(16) uint8_t g_enc_lo[(size_t)M_ * K2_ * 2];

// ---------------------------------------------------------------- smem layout
// A: [stage][plane][64 rows][128B]  -> 4 x 8KB  = 32KB
// B: [stage][plane][128 rows][128B] -> 4 x 16KB = 64KB
#define SA(st, pl)  ((st) * 16384 + (pl) * 8192)
#define SB(st, pl)  (32768 + (st) * 32768 + (pl) * 16384)
#define SM_SV   98304       // 512 f32
#define SM_HW0  100352      // 512 f32
#define SM_HW1  102400      // 512 f32
#define SM_RS   104448      // 64 f32
#define SM_TOTAL 104704

// ---------------------------------------------------------------- helpers
__device__ __forceinline__ uint32_t smem_u32(const void* p) {
    uint32_t a;
    asm("{ .reg .u64 t; cvta.to.shared.u64 t, %1; cvt.u32.u64 %0, t; }" : "=r"(a) : "l"(p));
    return a;
}
__host__ __device__ __forceinline__ uint32_t swz128(uint32_t off) {
    return off ^ ((off >> 3) & 0x70);
}
#define LDSM4(R, A)                                                             \
    asm volatile("ldmatrix.sync.aligned.m8n8.x4.shared.b16 {%0,%1,%2,%3}, [%4];" \
        : "=r"((R)[0]), "=r"((R)[1]), "=r"((R)[2]), "=r"((R)[3]) : "r"(A))
__device__ __forceinline__ void mma_bf16(float* c, const uint32_t* a, const uint32_t* b) {
    asm volatile("mma.sync.aligned.m16n8k16.row.col.f32.bf16.bf16.f32 "
        "{%0,%1,%2,%3},{%4,%5,%6,%7},{%8,%9},{%0,%1,%2,%3};"
        : "+f"(c[0]), "+f"(c[1]), "+f"(c[2]), "+f"(c[3])
        : "r"(a[0]), "r"(a[1]), "r"(a[2]), "r"(a[3]), "r"(b[0]), "r"(b[1]));
}
#define CP16(dst, src) \
    asm volatile("cp.async.cg.shared.global [%0], [%1], 16;" :: "r"(dst), "l"(src) : "memory")
#define CP_COMMIT() asm volatile("cp.async.commit_group;" ::: "memory")
#define CP_WAIT0()  asm volatile("cp.async.wait_group 0;" ::: "memory")

// ---------------------------------------------------------------------------
// FUSED prep kernel:
//   conv_enc [0,8000) | hw [8000,8256) | conv_w [8256,8320) | zero [8320,8352)
// ---------------------------------------------------------------------------
__global__ __launch_bounds__(512)
void prep_kernel(const float* __restrict__ enc,
                 const float* __restrict__ hidden,
                 const float* __restrict__ attn_w,
                 const float* __restrict__ attn_b) {
    const int bx = blockIdx.x;
    const int tid = threadIdx.x;

    if (bx < 8000) {
        // ---- conv_enc: 8 rows per block --------------------------------
        const int r = bx * 8 + (tid >> 6);
        const int c = (tid & 63) * 16;
        const float4* p = reinterpret_cast<const float4*>(enc + (size_t)r * K2_ + c);
        uint2* dh = reinterpret_cast<uint2*>(g_enc_hi + (size_t)r * (K2_ * 2) + c * 2);
        uint2* dl = reinterpret_cast<uint2*>(g_enc_lo + (size_t)r * (K2_ * 2) + c * 2);
        #pragma unroll
        for (int j = 0; j < 4; j++) {
            float4 f = p[j];
            __nv_bfloat16 h0 = __float2bfloat16(f.x);
            __nv_bfloat16 h1 = __float2bfloat16(f.y);
            __nv_bfloat16 h2 = __float2bfloat16(f.z);
            __nv_bfloat16 h3 = __float2bfloat16(f.w);
            __nv_bfloat16 l0 = __float2bfloat16(f.x - __bfloat162float(h0));
            __nv_bfloat16 l1 = __float2bfloat16(f.y - __bfloat162float(h1));
            __nv_bfloat16 l2 = __float2bfloat16(f.z - __bfloat162float(h2));
            __nv_bfloat16 l3 = __float2bfloat16(f.w - __bfloat162float(h3));
            __nv_bfloat162 hp0 = __halves2bfloat162(h0, h1);
            __nv_bfloat162 hp1 = __halves2bfloat162(h2, h3);
            __nv_bfloat162 lp0 = __halves2bfloat162(l0, l1);
            __nv_bfloat162 lp1 = __halves2bfloat162(l2, l3);
            dh[j] = make_uint2(*reinterpret_cast<uint32_t*>(&hp0),
                               *reinterpret_cast<uint32_t*>(&hp1));
            dl[j] = make_uint2(*reinterpret_cast<uint32_t*>(&lp0),
                               *reinterpret_cast<uint32_t*>(&lp1));
        }
    } else if (bx < 8256) {
        // ---- hW: 512 thr = 128 n-cols x 4 k-slices ----------------------
        __shared__ float sh[D_];
        __shared__ float part[3][128];
        const int bi = bx - 8000;
        const int b  = bi >> 2;
        const int ng = bi & 3;
        const int nl = tid & 127;
        const int ks = tid >> 7;
        const int n  = ng * 128 + nl;
        for (int i = tid; i < D_; i += 512) sh[i] = hidden[b * D_ + i];
        __syncthreads();
        const int k0 = ks * 128;
        float a0 = 0.f, a1 = 0.f, a2 = 0.f, a3 = 0.f;
        #pragma unroll 8
        for (int k = k0; k < k0 + 128; k += 4) {
            a0 += sh[k + 0] * attn_w[(k + 0) * D_ + n];
            a1 += sh[k + 1] * attn_w[(k + 1) * D_ + n];
            a2 += sh[k + 2] * attn_w[(k + 2) * D_ + n];
            a3 += sh[k + 3] * attn_w[(k + 3) * D_ + n];
        }
        float acc = (a0 + a1) + (a2 + a3);
        if (ks) part[ks - 1][nl] = acc;
        __syncthreads();
        if (ks == 0)
            g_hW[b * D_ + n] = attn_b[n] + acc + part[0][nl] + part[1][nl] + part[2][nl];
    } else if (bx < 8320) {
        // ---- conv_w: split + transpose + swizzle W_bot ------------------
        const int bi = bx - 8256;
        const int chunk = bi >> 2;
        const int kg0 = (bi & 3) * 16;
        const int n = tid;
        uint8_t* dh = g_wprep_hi + chunk * (D_ * 128);
        uint8_t* dl = g_wprep_lo + chunk * (D_ * 128);
        for (int kk = kg0; kk < kg0 + 16; kk++) {
            const int kg = D_ + chunk * KC + kk;
            float w = attn_w[(size_t)kg * D_ + n];
            __nv_bfloat16 hi = __float2bfloat16(w);
            __nv_bfloat16 lo = __float2bfloat16(w - __bfloat162float(hi));
            uint32_t sw = swz128((uint32_t)(n * 128 + kk * 2));
            *reinterpret_cast<uint16_t*>(dh + sw) = *reinterpret_cast<uint16_t*>(&hi);
            *reinterpret_cast<uint16_t*>(dl + sw) = *reinterpret_cast<uint16_t*>(&lo);
        }
    } else {
        // ---- zero g_logits (split-N gemm accumulates via atomicAdd) -----
        const int bi = bx - 8320;
        int idx = bi * 2048 + tid;
        #pragma unroll
        for (int j = 0; j < 4; j++) {
            if (idx < M_) g_logits[idx] = 0.f;
            idx += 512;
        }
    }
}

// ---------------------------------------------------------------------------
// Main HMMA GEMM + tanh + v-dot.  grid(2000), block(256), 2 CTAs/SM.
// Split-N: CTA (t,h) handles m-tile t (64 rows), N-passes {2h, 2h+1};
// partial rowsums atomicAdd'ed into g_logits (zeroed by prep).
// Pass-transition loads pipelined into the chunk-15 slot (stage 0 is free).
// ---------------------------------------------------------------------------
__global__ __launch_bounds__(NT, 2)
void gemm_kernel(const float* __restrict__ v) {
    extern __shared__ __align__(1024) uint8_t smem[];
    const uint32_t sb = smem_u32(smem);
    const int tid  = threadIdx.x;
    const int wid  = tid >> 5;
    const int lane = tid & 31;
    const int wm   = wid >> 2;          // 0..1 (32 M rows each)
    const int wn   = wid & 3;           // 0..3 (32 N cols each)
    const int m0   = (blockIdx.x >> 1) * TMM;
    const int p0   = (blockIdx.x & 1) * PPC;   // first N-pass of this CTA

    float* svp = reinterpret_cast<float*>(smem + SM_SV);
    float* hw0 = reinterpret_cast<float*>(smem + SM_HW0);
    float* hw1 = reinterpret_cast<float*>(smem + SM_HW1);
    float* rsm = reinterpret_cast<float*>(smem + SM_RS);

    // ---- per-lane ldmatrix address components ------------------------------
    const int a_r16 = lane & 15;
    const uint32_t a_kext = (lane >> 4) << 4;
    uint32_t aoff[2], aswz[2];
    #pragma unroll
    for (int ms = 0; ms < 2; ms++) {
        int r = wm * 32 + ms * 16 + a_r16;
        aoff[ms] = (uint32_t)r * 128;
        aswz[ms] = (uint32_t)(r & 7) << 4;
    }
    const int b_r16 = (lane & 7) | ((lane & 16) >> 1);
    const uint32_t b_kext = (lane & 8) << 1;
    uint32_t boff[2], bsw[2];
    #pragma unroll
    for (int np = 0; np < 2; np++) {
        int r = wn * 32 + np * 16 + b_r16;
        boff[np] = (uint32_t)r * 128;
        bsw[np]  = (uint32_t)(r & 7) << 4;
    }

    // ---- cp.async loader ----------------------------------------------------
    auto loadAB = [&](int pass, int chunk, int st) {
        #pragma unroll
        for (int j = 0; j < 2; j++) {
            uint32_t p = (uint32_t)tid + j * NT;
            uint32_t row = p >> 3, c16 = p & 7;
            uint32_t dsto = row * 128 + ((c16 << 4) ^ ((row & 7) << 4));
            size_t   srco = (size_t)(m0 + row) * (K2_ * 2) + chunk * 128 + (c16 << 4);
            CP16(sb + SA(st, 0) + dsto, g_enc_hi + srco);
            CP16(sb + SA(st, 1) + dsto, g_enc_lo + srco);
        }
        const uint8_t* gh = g_wprep_hi + chunk * (D_ * 128) + pass * (128 * 128);
        const uint8_t* gl = g_wprep_lo + chunk * (D_ * 128) + pass * (128 * 128);
        #pragma unroll
        for (int j = 0; j < 4; j++) {
            uint32_t idx = (uint32_t)(tid + j * NT) * 16;   // straight copy keeps swizzle
            CP16(sb + SB(st, 0) + idx, gh + idx);
            CP16(sb + SB(st, 1) + idx, gl + idx);
        }
        CP_COMMIT();
    };

    // kick off the first chunk immediately, then stage the small smem tables
    loadAB(p0, 0, 0);

    const int b0 = m0 / S_;
    const int b1 = (m0 + TMM - 1) / S_;
    const int thr = (b0 + 1) * S_ - m0;   // rows >= thr belong to b1
    for (int i = tid; i < D_; i += NT) {
        svp[i] = v[i];
        hw0[i] = g_hW[b0 * D_ + i];
        hw1[i] = g_hW[b1 * D_ + i];
    }
    if (tid < TMM) rsm[tid] = 0.f;

    float acc[2][4][4];   // [ms][np*2+half][4]

    auto compute = [&](int st) {
        const uint32_t baseAh = sb + SA(st, 0);
        const uint32_t baseAl = sb + SA(st, 1);
        const uint32_t baseBh = sb + SB(st, 0);
        const uint32_t baseBl = sb + SB(st, 1);
        #pragma unroll
        for (int k16 = 0; k16 < 4; k16++) {
            const uint32_t ka = (uint32_t)(k16 * 32) + a_kext;
            const uint32_t kb = (uint32_t)(k16 * 32) + b_kext;
            uint32_t ah[2][4], al[2][4];
            #pragma unroll
            for (int ms = 0; ms < 2; ms++) {
                uint32_t o = aoff[ms] + (ka ^ aswz[ms]);
                LDSM4(ah[ms], baseAh + o);
                LDSM4(al[ms], baseAl + o);
            }
            #pragma unroll
            for (int np = 0; np < 2; np++) {
                const uint32_t o = boff[np] + (kb ^ bsw[np]);
                uint32_t bh[4], bl[4];
                LDSM4(bh, baseBh + o);
                #pragma unroll
                for (int ms = 0; ms < 2; ms++) {
                    mma_bf16(acc[ms][np * 2 + 0], ah[ms], bh + 0);
                    mma_bf16(acc[ms][np * 2 + 1], ah[ms], bh + 2);
                    mma_bf16(acc[ms][np * 2 + 0], al[ms], bh + 0);
                    mma_bf16(acc[ms][np * 2 + 1], al[ms], bh + 2);
                }
                LDSM4(bl, baseBl + o);
                #pragma unroll
                for (int ms = 0; ms < 2; ms++) {
                    mma_bf16(acc[ms][np * 2 + 0], ah[ms], bl + 0);
                    mma_bf16(acc[ms][np * 2 + 1], ah[ms], bl + 2);
                }
            }
        }
    };

    const int gid = lane >> 2;
    const int tig = lane & 3;

    // ======================= PPC N-passes (128 cols each) ===================
    #pragma unroll 1
    for (int pi = 0; pi < PPC; pi++) {
        const int pass = p0 + pi;
        #pragma unroll
        for (int ms = 0; ms < 2; ms++)
            #pragma unroll
            for (int f = 0; f < 4; f++)
                #pragma unroll
                for (int c = 0; c < 4; c++) acc[ms][f][c] = 0.f;

        // ONE sync per chunk; next pass's chunk 0 is issued in the i=15 slot
        // (stage 0's last reader was compute(14), proven done by the barrier).
        #pragma unroll 1
        for (int i = 0; i < NCH; i++) {
            const int s = i & 1;
            CP_WAIT0();
            __syncthreads();
            if (i + 1 < NCH)      loadAB(pass, i + 1, s ^ 1);
            else if (pi + 1 < PPC) loadAB(pass + 1, 0, 0);
            compute(s);
        }

        // epilogue: x = acc + hW, rowsum += v * tanh(x)   (smem accumulation)
        #pragma unroll
        for (int ms = 0; ms < 2; ms++) {
            #pragma unroll
            for (int ch = 0; ch < 2; ch++) {
                const int r = wm * 32 + ms * 16 + ch * 8 + gid;
                const float* hwrow = (r >= thr) ? hw1 : hw0;
                float rs = 0.f;
                #pragma unroll
                for (int f = 0; f < 4; f++) {
                    const int n = pass * 128 + wn * 32 + f * 8 + tig * 2;
                    float x0 = acc[ms][f][ch * 2 + 0] + hwrow[n];
                    float x1 = acc[ms][f][ch * 2 + 1] + hwrow[n + 1];
                    rs += svp[n] * tanhf(x0) + svp[n + 1] * tanhf(x1);
                }
                rs += __shfl_xor_sync(0xffffffffu, rs, 1);
                rs += __shfl_xor_sync(0xffffffffu, rs, 2);
                if (tig == 0) atomicAdd(&rsm[r], rs);
            }
        }
    }

    __syncthreads();
    if (tid < TMM) atomicAdd(&g_logits[m0 + tid], rsm[tid]);
}

// ---------------------------------------------------------------------------
// softmax over S per batch. grid(64), block(256)
// ---------------------------------------------------------------------------
__global__ void softmax_kernel(float* __restrict__ out) {
    __shared__ float red[256];
    const int b = blockIdx.x;
    const int t = threadIdx.x;
    const float* row = g_logits + b * S_;
    float* orow = out + b * S_;

    float mx = -INFINITY;
    for (int i = t; i < S_; i += 256) mx = fmaxf(mx, row[i]);
    red[t] = mx;
    __syncthreads();
    for (int off = 128; off > 0; off >>= 1) {
        if (t < off) red[t] = fmaxf(red[t], red[t + off]);
        __syncthreads();
    }
    mx = red[0];
    __syncthreads();

    float sum = 0.f;
    for (int i = t; i < S_; i += 256) {
        float e = expf(row[i] - mx);
        orow[i] = e;
        sum += e;
    }
    red[t] = sum;
    __syncthreads();
    for (int off = 128; off > 0; off >>= 1) {
        if (t < off) red[t] += red[t + off];
        __syncthreads();
    }
    const float inv = 1.f / red[0];
    __syncthreads();
    for (int i = t; i < S_; i += 256) orow[i] *= inv;
}

// ---------------------------------------------------------------------------
extern "C" void kernel_launch(void* const* d_in, const int* in_sizes, int n_in,
                              void* d_out, int out_size) {
    const float* hidden = (const float*)d_in[0];   // [64, 512]
    const float* enc    = (const float*)d_in[1];   // [64, 1000, 1024]
    const float* attn_w = (const float*)d_in[2];   // [1536, 512]
    const float* attn_b = (const float*)d_in[3];   // [512]
    const float* v      = (const float*)d_in[4];   // [512]
    float* out = (float*)d_out;                    // [64, 1000]

    cudaFuncSetAttribute(gemm_kernel,
                         cudaFuncAttributeMaxDynamicSharedMemorySize, SM_TOTAL);

    prep_kernel<<<8352, 512>>>(enc, hidden, attn_w, attn_b);
    gemm_kernel<<<(M_ / TMM) * 2, NT, SM_TOTAL>>>(v);
    softmax_kernel<<<B_, 256>>>(out);
}

// round 13
// speedup vs baseline: 1.0218x; 1.0109x over previous
#include <cuda_runtime.h>
#include <cuda_bf16.h>
#include <math.h>
#include <stdint.h>

// ---------------------------------------------------------------- constants
#define B_   64
#define S_   1000
#define D_   512          // N of the GEMM
#define K2_  1024         // K of the GEMM
#define M_   (B_ * S_)    // 64000

#define TMM  64           // CTA M tile (small -> 2 CTAs/SM)
#define KC   64           // K chunk (64 bf16 = 128B swizzled rows)
#define NCH  16           // K2_/KC
#define NT   256          // threads per CTA (8 warps = 2M x 4N)
#define PPC  2            // N-passes per CTA (split-N: 2 CTAs per m-tile)

// ------------------------------------------------------------- device scratch
__device__ float g_hW[B_ * D_];
__device__ float g_logits[M_];
// W_bot pre-split (hi/lo bf16), transposed [n][k], SW128-swizzled per chunk
__device__ __align__(16) uint8_t g_wprep_hi[NCH * D_ * 128];
__device__ __align__(16) uint8_t g_wprep_lo[NCH * D_ * 128];
// NOTE: enc is consumed fp32 directly by the gemm (in-kernel split) — no
// pre-converted planes, no 500 MB of extra HBM traffic.

// ---------------------------------------------------------------- smem layout
// A: [stage][plane][64 rows][128B]  -> 4 x 8KB  = 32KB
// B: [stage][plane][128 rows][128B] -> 4 x 16KB = 64KB
#define SA(st, pl)  ((st) * 16384 + (pl) * 8192)
#define SB(st, pl)  (32768 + (st) * 32768 + (pl) * 16384)
#define SM_SV   98304       // 512 f32
#define SM_HW0  100352      // 512 f32
#define SM_HW1  102400      // 512 f32
#define SM_RS   104448      // 64 f32
#define SM_TOTAL 104704

// ---------------------------------------------------------------- helpers
__device__ __forceinline__ uint32_t smem_u32(const void* p) {
    uint32_t a;
    asm("{ .reg .u64 t; cvta.to.shared.u64 t, %1; cvt.u32.u64 %0, t; }" : "=r"(a) : "l"(p));
    return a;
}
__host__ __device__ __forceinline__ uint32_t swz128(uint32_t off) {
    return off ^ ((off >> 3) & 0x70);
}
#define LDSM4(R, A)                                                             \
    asm volatile("ldmatrix.sync.aligned.m8n8.x4.shared.b16 {%0,%1,%2,%3}, [%4];" \
        : "=r"((R)[0]), "=r"((R)[1]), "=r"((R)[2]), "=r"((R)[3]) : "r"(A))
__device__ __forceinline__ void mma_bf16(float* c, const uint32_t* a, const uint32_t* b) {
    asm volatile("mma.sync.aligned.m16n8k16.row.col.f32.bf16.bf16.f32 "
        "{%0,%1,%2,%3},{%4,%5,%6,%7},{%8,%9},{%0,%1,%2,%3};"
        : "+f"(c[0]), "+f"(c[1]), "+f"(c[2]), "+f"(c[3])
        : "r"(a[0]), "r"(a[1]), "r"(a[2]), "r"(a[3]), "r"(b[0]), "r"(b[1]));
}
#define CP16(dst, src) \
    asm volatile("cp.async.cg.shared.global [%0], [%1], 16;" :: "r"(dst), "l"(src) : "memory")
#define CP_COMMIT() asm volatile("cp.async.commit_group;" ::: "memory")
#define CP_WAIT0()  asm volatile("cp.async.wait_group 0;" ::: "memory")

// fp32 pair -> packed bf16x2 hi + lo planes
__device__ __forceinline__ void cvt2(float a, float b, uint32_t& h, uint32_t& l) {
    __nv_bfloat16 ha = __float2bfloat16(a), hb = __float2bfloat16(b);
    __nv_bfloat16 la = __float2bfloat16(a - __bfloat162float(ha));
    __nv_bfloat16 lb = __float2bfloat16(b - __bfloat162float(hb));
    __nv_bfloat162 hp = __halves2bfloat162(ha, hb);
    __nv_bfloat162 lp = __halves2bfloat162(la, lb);
    h = *reinterpret_cast<uint32_t*>(&hp);
    l = *reinterpret_cast<uint32_t*>(&lp);
}

// ---------------------------------------------------------------------------
// FUSED prep kernel: hw [0,256) | conv_w [256,320) | zero logits [320,352)
// (conv_enc is gone — the gemm converts A in-kernel.)
// ---------------------------------------------------------------------------
__global__ __launch_bounds__(512)
void prep_kernel(const float* __restrict__ hidden,
                 const float* __restrict__ attn_w,
                 const float* __restrict__ attn_b) {
    const int bx = blockIdx.x;
    const int tid = threadIdx.x;

    if (bx < 256) {
        // ---- hW: 512 thr = 128 n-cols x 4 k-slices ----------------------
        __shared__ float sh[D_];
        __shared__ float part[3][128];
        const int b  = bx >> 2;
        const int ng = bx & 3;
        const int nl = tid & 127;
        const int ks = tid >> 7;
        const int n  = ng * 128 + nl;
        for (int i = tid; i < D_; i += 512) sh[i] = hidden[b * D_ + i];
        __syncthreads();
        const int k0 = ks * 128;
        float a0 = 0.f, a1 = 0.f, a2 = 0.f, a3 = 0.f;
        #pragma unroll 8
        for (int k = k0; k < k0 + 128; k += 4) {
            a0 += sh[k + 0] * attn_w[(k + 0) * D_ + n];
            a1 += sh[k + 1] * attn_w[(k + 1) * D_ + n];
            a2 += sh[k + 2] * attn_w[(k + 2) * D_ + n];
            a3 += sh[k + 3] * attn_w[(k + 3) * D_ + n];
        }
        float acc = (a0 + a1) + (a2 + a3);
        if (ks) part[ks - 1][nl] = acc;
        __syncthreads();
        if (ks == 0)
            g_hW[b * D_ + n] = attn_b[n] + acc + part[0][nl] + part[1][nl] + part[2][nl];
    } else if (bx < 320) {
        // ---- conv_w: split + transpose + swizzle W_bot ------------------
        const int bi = bx - 256;
        const int chunk = bi >> 2;
        const int kg0 = (bi & 3) * 16;
        const int n = tid;
        uint8_t* dh = g_wprep_hi + chunk * (D_ * 128);
        uint8_t* dl = g_wprep_lo + chunk * (D_ * 128);
        for (int kk = kg0; kk < kg0 + 16; kk++) {
            const int kg = D_ + chunk * KC + kk;
            float w = attn_w[(size_t)kg * D_ + n];
            __nv_bfloat16 hi = __float2bfloat16(w);
            __nv_bfloat16 lo = __float2bfloat16(w - __bfloat162float(hi));
            uint32_t sw = swz128((uint32_t)(n * 128 + kk * 2));
            *reinterpret_cast<uint16_t*>(dh + sw) = *reinterpret_cast<uint16_t*>(&hi);
            *reinterpret_cast<uint16_t*>(dl + sw) = *reinterpret_cast<uint16_t*>(&lo);
        }
    } else {
        // ---- zero g_logits (split-N gemm accumulates via atomicAdd) -----
        const int bi = bx - 320;
        int idx = bi * 2048 + tid;
        #pragma unroll
        for (int j = 0; j < 4; j++) {
            if (idx < M_) g_logits[idx] = 0.f;
            idx += 512;
        }
    }
}

// ---------------------------------------------------------------------------
// Main HMMA GEMM + tanh + v-dot.  grid(2000), block(256), 2 CTAs/SM.
// A path: LDG fp32 enc (chunk i+1, prefetched across compute(i)) -> register
// bf16 hi/lo split -> swizzled STS. B path: cp.async of pre-swizzled images.
// ---------------------------------------------------------------------------
__global__ __launch_bounds__(NT, 2)
void gemm_kernel(const float* __restrict__ enc, const float* __restrict__ v) {
    extern __shared__ __align__(1024) uint8_t smem[];
    const uint32_t sb = smem_u32(smem);
    const int tid  = threadIdx.x;
    const int wid  = tid >> 5;
    const int lane = tid & 31;
    const int wm   = wid >> 2;          // 0..1 (32 M rows each)
    const int wn   = wid & 3;           // 0..3 (32 N cols each)
    const int m0   = (blockIdx.x >> 1) * TMM;
    const int p0   = (blockIdx.x & 1) * PPC;   // first N-pass of this CTA

    float* svp = reinterpret_cast<float*>(smem + SM_SV);
    float* hw0 = reinterpret_cast<float*>(smem + SM_HW0);
    float* hw1 = reinterpret_cast<float*>(smem + SM_HW1);
    float* rsm = reinterpret_cast<float*>(smem + SM_RS);

    // ---- A conversion mapping: thread -> (row, 16-float k-group) ----------
    const int arow = tid >> 2;              // 0..63
    const int ak16 = tid & 3;               // 16-float group within chunk
    const float* abase = enc + (size_t)(m0 + arow) * K2_ + ak16 * 16;
    const uint32_t adst0 = (uint32_t)arow * 128 +
                           (((uint32_t)(ak16 * 2 + 0) << 4) ^ ((uint32_t)(arow & 7) << 4));
    const uint32_t adst1 = (uint32_t)arow * 128 +
                           (((uint32_t)(ak16 * 2 + 1) << 4) ^ ((uint32_t)(arow & 7) << 4));

    // ---- B cp.async loader (pre-swizzled images: straight copy) -----------
    auto loadB = [&](int pass, int chunk, int st) {
        const uint8_t* gh = g_wprep_hi + chunk * (D_ * 128) + pass * (128 * 128);
        const uint8_t* gl = g_wprep_lo + chunk * (D_ * 128) + pass * (128 * 128);
        #pragma unroll
        for (int j = 0; j < 4; j++) {
            uint32_t idx = (uint32_t)(tid + j * NT) * 16;
            CP16(sb + SB(st, 0) + idx, gh + idx);
            CP16(sb + SB(st, 1) + idx, gl + idx);
        }
        CP_COMMIT();
    };
    // A: register bf16 split + swizzled STS (two 16B pieces per plane)
    auto stA = [&](const float4& f0, const float4& f1,
                   const float4& f2, const float4& f3, int st) {
        uint4 h0, l0, h1, l1;
        cvt2(f0.x, f0.y, h0.x, l0.x);
        cvt2(f0.z, f0.w, h0.y, l0.y);
        cvt2(f1.x, f1.y, h0.z, l0.z);
        cvt2(f1.z, f1.w, h0.w, l0.w);
        cvt2(f2.x, f2.y, h1.x, l1.x);
        cvt2(f2.z, f2.w, h1.y, l1.y);
        cvt2(f3.x, f3.y, h1.z, l1.z);
        cvt2(f3.z, f3.w, h1.w, l1.w);
        *reinterpret_cast<uint4*>(smem + SA(st, 0) + adst0) = h0;
        *reinterpret_cast<uint4*>(smem + SA(st, 1) + adst0) = l0;
        *reinterpret_cast<uint4*>(smem + SA(st, 0) + adst1) = h1;
        *reinterpret_cast<uint4*>(smem + SA(st, 1) + adst1) = l1;
    };

    // ---- per-lane ldmatrix address components ------------------------------
    const int a_r16 = lane & 15;
    const uint32_t a_kext = (lane >> 4) << 4;
    uint32_t aoff[2], aswz[2];
    #pragma unroll
    for (int ms = 0; ms < 2; ms++) {
        int r = wm * 32 + ms * 16 + a_r16;
        aoff[ms] = (uint32_t)r * 128;
        aswz[ms] = (uint32_t)(r & 7) << 4;
    }
    const int b_r16 = (lane & 7) | ((lane & 16) >> 1);
    const uint32_t b_kext = (lane & 8) << 1;
    uint32_t boff[2], bsw[2];
    #pragma unroll
    for (int np = 0; np < 2; np++) {
        int r = wn * 32 + np * 16 + b_r16;
        boff[np] = (uint32_t)r * 128;
        bsw[np]  = (uint32_t)(r & 7) << 4;
    }

    // ---- CTA prologue: chunk 0 of pass p0 ----------------------------------
    {
        const float* ap = abase;   // chunk 0
        float4 f0 = reinterpret_cast<const float4*>(ap)[0];
        float4 f1 = reinterpret_cast<const float4*>(ap)[1];
        float4 f2 = reinterpret_cast<const float4*>(ap)[2];
        float4 f3 = reinterpret_cast<const float4*>(ap)[3];
        loadB(p0, 0, 0);
        // stage small tables while the A LDGs are in flight
        const int b0i = m0 / S_;
        const int b1i = (m0 + TMM - 1) / S_;
        for (int i = tid; i < D_; i += NT) {
            svp[i] = v[i];
            hw0[i] = g_hW[b0i * D_ + i];
            hw1[i] = g_hW[b1i * D_ + i];
        }
        if (tid < TMM) rsm[tid] = 0.f;
        stA(f0, f1, f2, f3, 0);
    }
    const int b0 = m0 / S_;
    const int thr = (b0 + 1) * S_ - m0;   // rows >= thr belong to batch b0+1

    float acc[2][4][4];   // [ms][np*2+half][4]

    auto compute = [&](int st) {
        const uint32_t baseAh = sb + SA(st, 0);
        const uint32_t baseAl = sb + SA(st, 1);
        const uint32_t baseBh = sb + SB(st, 0);
        const uint32_t baseBl = sb + SB(st, 1);
        #pragma unroll
        for (int k16 = 0; k16 < 4; k16++) {
            const uint32_t ka = (uint32_t)(k16 * 32) + a_kext;
            const uint32_t kb = (uint32_t)(k16 * 32) + b_kext;
            uint32_t ah[2][4], al[2][4];
            #pragma unroll
            for (int ms = 0; ms < 2; ms++) {
                uint32_t o = aoff[ms] + (ka ^ aswz[ms]);
                LDSM4(ah[ms], baseAh + o);
                LDSM4(al[ms], baseAl + o);
            }
            #pragma unroll
            for (int np = 0; np < 2; np++) {
                const uint32_t o = boff[np] + (kb ^ bsw[np]);
                uint32_t bh[4], bl[4];
                LDSM4(bh, baseBh + o);
                #pragma unroll
                for (int ms = 0; ms < 2; ms++) {
                    mma_bf16(acc[ms][np * 2 + 0], ah[ms], bh + 0);
                    mma_bf16(acc[ms][np * 2 + 1], ah[ms], bh + 2);
                    mma_bf16(acc[ms][np * 2 + 0], al[ms], bh + 0);
                    mma_bf16(acc[ms][np * 2 + 1], al[ms], bh + 2);
                }
                LDSM4(bl, baseBl + o);
                #pragma unroll
                for (int ms = 0; ms < 2; ms++) {
                    mma_bf16(acc[ms][np * 2 + 0], ah[ms], bl + 0);
                    mma_bf16(acc[ms][np * 2 + 1], ah[ms], bl + 2);
                }
            }
        }
    };

    const int gid = lane >> 2;
    const int tig = lane & 3;

    // ======================= PPC N-passes (128 cols each) ===================
    #pragma unroll 1
    for (int pi = 0; pi < PPC; pi++) {
        const int pass = p0 + pi;
        #pragma unroll
        for (int ms = 0; ms < 2; ms++)
            #pragma unroll
            for (int f = 0; f < 4; f++)
                #pragma unroll
                for (int c = 0; c < 4; c++) acc[ms][f][c] = 0.f;

        // ONE sync per chunk. Next chunk's A is LDG'd before compute (latency
        // hidden across the MMAs) and converted+stored after compute into the
        // stage that the barrier just proved free.
        #pragma unroll 1
        for (int i = 0; i < NCH; i++) {
            const int s = i & 1;
            CP_WAIT0();
            __syncthreads();
            int nchunk = -1, npass = pass, nst = s ^ 1;
            if (i + 1 < NCH)       { nchunk = i + 1; }
            else if (pi + 1 < PPC) { nchunk = 0; npass = pass + 1; nst = 0; }
            float4 f0, f1, f2, f3;
            if (nchunk >= 0) {
                const float* ap = abase + nchunk * KC;
                f0 = reinterpret_cast<const float4*>(ap)[0];
                f1 = reinterpret_cast<const float4*>(ap)[1];
                f2 = reinterpret_cast<const float4*>(ap)[2];
                f3 = reinterpret_cast<const float4*>(ap)[3];
                loadB(npass, nchunk, nst);
            }
            compute(s);
            if (nchunk >= 0) stA(f0, f1, f2, f3, nst);
        }

        // epilogue: x = acc + hW, rowsum += v * tanh(x)   (smem accumulation)
        #pragma unroll
        for (int ms = 0; ms < 2; ms++) {
            #pragma unroll
            for (int ch = 0; ch < 2; ch++) {
                const int r = wm * 32 + ms * 16 + ch * 8 + gid;
                const float* hwrow = (r >= thr) ? hw1 : hw0;
                float rs = 0.f;
                #pragma unroll
                for (int f = 0; f < 4; f++) {
                    const int n = pass * 128 + wn * 32 + f * 8 + tig * 2;
                    float x0 = acc[ms][f][ch * 2 + 0] + hwrow[n];
                    float x1 = acc[ms][f][ch * 2 + 1] + hwrow[n + 1];
                    rs += svp[n] * tanhf(x0) + svp[n + 1] * tanhf(x1);
                }
                rs += __shfl_xor_sync(0xffffffffu, rs, 1);
                rs += __shfl_xor_sync(0xffffffffu, rs, 2);
                if (tig == 0) atomicAdd(&rsm[r], rs);
            }
        }
    }

    __syncthreads();
    if (tid < TMM) atomicAdd(&g_logits[m0 + tid], rsm[tid]);
}

// ---------------------------------------------------------------------------
// softmax over S per batch. grid(64), block(256)
// ---------------------------------------------------------------------------
__global__ void softmax_kernel(float* __restrict__ out) {
    __shared__ float red[256];
    const int b = blockIdx.x;
    const int t = threadIdx.x;
    const float* row = g_logits + b * S_;
    float* orow = out + b * S_;

    float mx = -INFINITY;
    for (int i = t; i < S_; i += 256) mx = fmaxf(mx, row[i]);
    red[t] = mx;
    __syncthreads();
    for (int off = 128; off > 0; off >>= 1) {
        if (t < off) red[t] = fmaxf(red[t], red[t + off]);
        __syncthreads();
    }
    mx = red[0];
    __syncthreads();

    float sum = 0.f;
    for (int i = t; i < S_; i += 256) {
        float e = expf(row[i] - mx);
        orow[i] = e;
        sum += e;
    }
    red[t] = sum;
    __syncthreads();
    for (int off = 128; off > 0; off >>= 1) {
        if (t < off) red[t] += red[t + off];
        __syncthreads();
    }
    const float inv = 1.f / red[0];
    __syncthreads();
    for (int i = t; i < S_; i += 256) orow[i] *= inv;
}

// ---------------------------------------------------------------------------
extern "C" void kernel_launch(void* const* d_in, const int* in_sizes, int n_in,
                              void* d_out, int out_size) {
    const float* hidden = (const float*)d_in[0];   // [64, 512]
    const float* enc    = (const float*)d_in[1];   // [64, 1000, 1024]
    const float* attn_w = (const float*)d_in[2];   // [1536, 512]
    const float* attn_b = (const float*)d_in[3];   // [512]
    const float* v      = (const float*)d_in[4];   // [512]
    float* out = (float*)d_out;                    // [64, 1000]

    cudaFuncSetAttribute(gemm_kernel,
                         cudaFuncAttributeMaxDynamicSharedMemorySize, SM_TOTAL);

    prep_kernel<<<352, 512>>>(hidden, attn_w, attn_b);
    gemm_kernel<<<(M_ / TMM) * 2, NT, SM_TOTAL>>>(enc, v);
    softmax_kernel<<<B_, 256>>>(out);
}

// round 14
// speedup vs baseline: 1.2968x; 1.2691x over previous
#include <cuda_runtime.h>
#include <cuda_fp16.h>
#include <math.h>
#include <stdint.h>

// ---------------------------------------------------------------- constants
#define B_   64
#define S_   1000
#define D_   512          // N of the GEMM
#define K2_  1024         // K of the GEMM
#define M_   (B_ * S_)    // 64000

#define TMM  64           // CTA M tile (2 CTAs/SM)
#define KC   64           // K chunk (64 fp16 = 128B swizzled rows)
#define NCH  16           // K2_/KC
#define NT   256          // threads per CTA (8 warps = 2M x 4N)
#define PPC  2            // N-passes per CTA (split-N: 2 CTAs per m-tile)

#define BSCALE     256.0f       // B pre-scale (keeps Bl out of fp16 subnormals)
#define BSCALE_INV 0.00390625f  // 1/256

// ------------------------------------------------------------- device scratch
__device__ float g_hW[B_ * D_];
__device__ float g_logits[M_];
// W_bot*256 pre-split (hi/lo fp16), transposed [n][k], SW128-swizzled per chunk
__device__ __align__(16) uint8_t g_wprep_hi[NCH * D_ * 128];
__device__ __align__(16) uint8_t g_wprep_lo[NCH * D_ * 128];

// ---------------------------------------------------------------- smem layout
// A: [stage][64 rows][128B]          -> 2 x 8KB  = 16KB   (single fp16 plane)
// B: [stage][plane][128 rows][128B]  -> 4 x 16KB = 64KB
#define SA(st)      ((st) * 8192)
#define SB(st, pl)  (16384 + (st) * 32768 + (pl) * 16384)
#define SM_SV   81920       // 512 f32
#define SM_HW0  83968       // 512 f32
#define SM_HW1  86016       // 512 f32
#define SM_RS   88064       // 64 f32
#define SM_TOTAL 88320

// ---------------------------------------------------------------- helpers
__device__ __forceinline__ uint32_t smem_u32(const void* p) {
    uint32_t a;
    asm("{ .reg .u64 t; cvta.to.shared.u64 t, %1; cvt.u32.u64 %0, t; }" : "=r"(a) : "l"(p));
    return a;
}
__host__ __device__ __forceinline__ uint32_t swz128(uint32_t off) {
    return off ^ ((off >> 3) & 0x70);
}
#define LDSM4(R, A)                                                             \
    asm volatile("ldmatrix.sync.aligned.m8n8.x4.shared.b16 {%0,%1,%2,%3}, [%4];" \
        : "=r"((R)[0]), "=r"((R)[1]), "=r"((R)[2]), "=r"((R)[3]) : "r"(A))
__device__ __forceinline__ void mma_f16(float* c, const uint32_t* a, const uint32_t* b) {
    asm volatile("mma.sync.aligned.m16n8k16.row.col.f32.f16.f16.f32 "
        "{%0,%1,%2,%3},{%4,%5,%6,%7},{%8,%9},{%0,%1,%2,%3};"
        : "+f"(c[0]), "+f"(c[1]), "+f"(c[2]), "+f"(c[3])
        : "r"(a[0]), "r"(a[1]), "r"(a[2]), "r"(a[3]), "r"(b[0]), "r"(b[1]));
}
#define CP16(dst, src) \
    asm volatile("cp.async.cg.shared.global [%0], [%1], 16;" :: "r"(dst), "l"(src) : "memory")
#define CP_COMMIT() asm volatile("cp.async.commit_group;" ::: "memory")
#define CP_WAIT0()  asm volatile("cp.async.wait_group 0;" ::: "memory")

// two fp32 -> packed fp16x2
__device__ __forceinline__ uint32_t pk2(float a, float b) {
    __half2 h = __halves2half2(__float2half(a), __float2half(b));
    return *reinterpret_cast<uint32_t*>(&h);
}

// ---------------------------------------------------------------------------
// FUSED prep kernel: hw [0,256) | conv_w [256,320) | zero logits [320,352)
// ---------------------------------------------------------------------------
__global__ __launch_bounds__(512)
void prep_kernel(const float* __restrict__ hidden,
                 const float* __restrict__ attn_w,
                 const float* __restrict__ attn_b) {
    const int bx = blockIdx.x;
    const int tid = threadIdx.x;

    if (bx < 256) {
        // ---- hW: 512 thr = 128 n-cols x 4 k-slices ----------------------
        __shared__ float sh[D_];
        __shared__ float part[3][128];
        const int b  = bx >> 2;
        const int ng = bx & 3;
        const int nl = tid & 127;
        const int ks = tid >> 7;
        const int n  = ng * 128 + nl;
        for (int i = tid; i < D_; i += 512) sh[i] = hidden[b * D_ + i];
        __syncthreads();
        const int k0 = ks * 128;
        float a0 = 0.f, a1 = 0.f, a2 = 0.f, a3 = 0.f;
        #pragma unroll 8
        for (int k = k0; k < k0 + 128; k += 4) {
            a0 += sh[k + 0] * attn_w[(k + 0) * D_ + n];
            a1 += sh[k + 1] * attn_w[(k + 1) * D_ + n];
            a2 += sh[k + 2] * attn_w[(k + 2) * D_ + n];
            a3 += sh[k + 3] * attn_w[(k + 3) * D_ + n];
        }
        float acc = (a0 + a1) + (a2 + a3);
        if (ks) part[ks - 1][nl] = acc;
        __syncthreads();
        if (ks == 0)
            g_hW[b * D_ + n] = attn_b[n] + acc + part[0][nl] + part[1][nl] + part[2][nl];
    } else if (bx < 320) {
        // ---- conv_w: W_bot*256 -> fp16 hi/lo, transpose + swizzle -------
        const int bi = bx - 256;
        const int chunk = bi >> 2;
        const int kg0 = (bi & 3) * 16;
        const int n = tid;
        uint8_t* dh = g_wprep_hi + chunk * (D_ * 128);
        uint8_t* dl = g_wprep_lo + chunk * (D_ * 128);
        for (int kk = kg0; kk < kg0 + 16; kk++) {
            const int kg = D_ + chunk * KC + kk;
            float w = attn_w[(size_t)kg * D_ + n] * BSCALE;
            __half hi = __float2half(w);
            __half lo = __float2half(w - __half2float(hi));
            uint32_t sw = swz128((uint32_t)(n * 128 + kk * 2));
            *reinterpret_cast<uint16_t*>(dh + sw) = *reinterpret_cast<uint16_t*>(&hi);
            *reinterpret_cast<uint16_t*>(dl + sw) = *reinterpret_cast<uint16_t*>(&lo);
        }
    } else {
        // ---- zero g_logits (split-N gemm accumulates via atomicAdd) -----
        const int bi = bx - 320;
        int idx = bi * 2048 + tid;
        #pragma unroll
        for (int j = 0; j < 4; j++) {
            if (idx < M_) g_logits[idx] = 0.f;
            idx += 512;
        }
    }
}

// ---------------------------------------------------------------------------
// Main HMMA GEMM + tanh + v-dot.  grid(2000), block(256), 2 CTAs/SM.
// fp16 2-term: A = fp16(enc) single plane (in-kernel cvt);
// B = (W*256) split into fp16 hi+lo (pre-swizzled). acc scaled by 1/256.
// ---------------------------------------------------------------------------
__global__ __launch_bounds__(NT, 2)
void gemm_kernel(const float* __restrict__ enc, const float* __restrict__ v) {
    extern __shared__ __align__(1024) uint8_t smem[];
    const uint32_t sb = smem_u32(smem);
    const int tid  = threadIdx.x;
    const int wid  = tid >> 5;
    const int lane = tid & 31;
    const int wm   = wid >> 2;          // 0..1 (32 M rows each)
    const int wn   = wid & 3;           // 0..3 (32 N cols each)
    const int m0   = (blockIdx.x >> 1) * TMM;
    const int p0   = (blockIdx.x & 1) * PPC;   // first N-pass of this CTA

    float* svp = reinterpret_cast<float*>(smem + SM_SV);
    float* hw0 = reinterpret_cast<float*>(smem + SM_HW0);
    float* hw1 = reinterpret_cast<float*>(smem + SM_HW1);
    float* rsm = reinterpret_cast<float*>(smem + SM_RS);

    // ---- A conversion mapping: thread -> (row, 16-float k-group) ----------
    const int arow = tid >> 2;              // 0..63
    const int ak16 = tid & 3;               // 16-float group within chunk
    const float* abase = enc + (size_t)(m0 + arow) * K2_ + ak16 * 16;
    const uint32_t adst0 = (uint32_t)arow * 128 +
                           (((uint32_t)(ak16 * 2 + 0) << 4) ^ ((uint32_t)(arow & 7) << 4));
    const uint32_t adst1 = (uint32_t)arow * 128 +
                           (((uint32_t)(ak16 * 2 + 1) << 4) ^ ((uint32_t)(arow & 7) << 4));

    // ---- B cp.async loader (pre-swizzled images: straight copy) -----------
    auto loadB = [&](int pass, int chunk, int st) {
        const uint8_t* gh = g_wprep_hi + chunk * (D_ * 128) + pass * (128 * 128);
        const uint8_t* gl = g_wprep_lo + chunk * (D_ * 128) + pass * (128 * 128);
        #pragma unroll
        for (int j = 0; j < 4; j++) {
            uint32_t idx = (uint32_t)(tid + j * NT) * 16;
            CP16(sb + SB(st, 0) + idx, gh + idx);
            CP16(sb + SB(st, 1) + idx, gl + idx);
        }
        CP_COMMIT();
    };
    // A: 16 fp32 -> 16 fp16 (single plane), two swizzled 16B stores
    auto stA = [&](const float4& f0, const float4& f1,
                   const float4& f2, const float4& f3, int st) {
        uint4 p0v, p1v;
        p0v.x = pk2(f0.x, f0.y);
        p0v.y = pk2(f0.z, f0.w);
        p0v.z = pk2(f1.x, f1.y);
        p0v.w = pk2(f1.z, f1.w);
        p1v.x = pk2(f2.x, f2.y);
        p1v.y = pk2(f2.z, f2.w);
        p1v.z = pk2(f3.x, f3.y);
        p1v.w = pk2(f3.z, f3.w);
        *reinterpret_cast<uint4*>(smem + SA(st) + adst0) = p0v;
        *reinterpret_cast<uint4*>(smem + SA(st) + adst1) = p1v;
    };

    // ---- per-lane ldmatrix address components ------------------------------
    const int a_r16 = lane & 15;
    const uint32_t a_kext = (lane >> 4) << 4;
    uint32_t aoff[2], aswz[2];
    #pragma unroll
    for (int ms = 0; ms < 2; ms++) {
        int r = wm * 32 + ms * 16 + a_r16;
        aoff[ms] = (uint32_t)r * 128;
        aswz[ms] = (uint32_t)(r & 7) << 4;
    }
    const int b_r16 = (lane & 7) | ((lane & 16) >> 1);
    const uint32_t b_kext = (lane & 8) << 1;
    uint32_t boff[2], bsw[2];
    #pragma unroll
    for (int np = 0; np < 2; np++) {
        int r = wn * 32 + np * 16 + b_r16;
        boff[np] = (uint32_t)r * 128;
        bsw[np]  = (uint32_t)(r & 7) << 4;
    }

    // ---- CTA prologue: chunk 0 of pass p0 ----------------------------------
    {
        const float* ap = abase;   // chunk 0
        float4 f0 = reinterpret_cast<const float4*>(ap)[0];
        float4 f1 = reinterpret_cast<const float4*>(ap)[1];
        float4 f2 = reinterpret_cast<const float4*>(ap)[2];
        float4 f3 = reinterpret_cast<const float4*>(ap)[3];
        loadB(p0, 0, 0);
        const int b0i = m0 / S_;
        const int b1i = (m0 + TMM - 1) / S_;
        for (int i = tid; i < D_; i += NT) {
            svp[i] = v[i];
            hw0[i] = g_hW[b0i * D_ + i];
            hw1[i] = g_hW[b1i * D_ + i];
        }
        if (tid < TMM) rsm[tid] = 0.f;
        stA(f0, f1, f2, f3, 0);
    }
    const int b0 = m0 / S_;
    const int thr = (b0 + 1) * S_ - m0;   // rows >= thr belong to batch b0+1

    float acc[2][4][4];   // [ms][np*2+half][4]

    auto compute = [&](int st) {
        const uint32_t baseA  = sb + SA(st);
        const uint32_t baseBh = sb + SB(st, 0);
        const uint32_t baseBl = sb + SB(st, 1);
        #pragma unroll
        for (int k16 = 0; k16 < 4; k16++) {
            const uint32_t ka = (uint32_t)(k16 * 32) + a_kext;
            const uint32_t kb = (uint32_t)(k16 * 32) + b_kext;
            uint32_t ah[2][4];
            #pragma unroll
            for (int ms = 0; ms < 2; ms++)
                LDSM4(ah[ms], baseA + aoff[ms] + (ka ^ aswz[ms]));
            #pragma unroll
            for (int np = 0; np < 2; np++) {
                const uint32_t o = boff[np] + (kb ^ bsw[np]);
                uint32_t bh[4], bl[4];
                LDSM4(bh, baseBh + o);
                LDSM4(bl, baseBl + o);
                #pragma unroll
                for (int ms = 0; ms < 2; ms++) {
                    mma_f16(acc[ms][np * 2 + 0], ah[ms], bh + 0);
                    mma_f16(acc[ms][np * 2 + 1], ah[ms], bh + 2);
                    mma_f16(acc[ms][np * 2 + 0], ah[ms], bl + 0);
                    mma_f16(acc[ms][np * 2 + 1], ah[ms], bl + 2);
                }
            }
        }
    };

    const int gid = lane >> 2;
    const int tig = lane & 3;

    // ======================= PPC N-passes (128 cols each) ===================
    #pragma unroll 1
    for (int pi = 0; pi < PPC; pi++) {
        const int pass = p0 + pi;
        #pragma unroll
        for (int ms = 0; ms < 2; ms++)
            #pragma unroll
            for (int f = 0; f < 4; f++)
                #pragma unroll
                for (int c = 0; c < 4; c++) acc[ms][f][c] = 0.f;

        // ONE sync per chunk; next chunk's A LDG issued before compute
        // (latency hidden), converted+stored after compute into the freed stage.
        #pragma unroll 1
        for (int i = 0; i < NCH; i++) {
            const int s = i & 1;
            CP_WAIT0();
            __syncthreads();
            int nchunk = -1, npass = pass, nst = s ^ 1;
            if (i + 1 < NCH)       { nchunk = i + 1; }
            else if (pi + 1 < PPC) { nchunk = 0; npass = pass + 1; nst = 0; }
            float4 f0, f1, f2, f3;
            if (nchunk >= 0) {
                const float* ap = abase + nchunk * KC;
                f0 = reinterpret_cast<const float4*>(ap)[0];
                f1 = reinterpret_cast<const float4*>(ap)[1];
                f2 = reinterpret_cast<const float4*>(ap)[2];
                f3 = reinterpret_cast<const float4*>(ap)[3];
                loadB(npass, nchunk, nst);
            }
            compute(s);
            if (nchunk >= 0) stA(f0, f1, f2, f3, nst);
        }

        // epilogue: x = acc/256 + hW, rowsum += v * tanh(x)
        #pragma unroll
        for (int ms = 0; ms < 2; ms++) {
            #pragma unroll
            for (int ch = 0; ch < 2; ch++) {
                const int r = wm * 32 + ms * 16 + ch * 8 + gid;
                const float* hwrow = (r >= thr) ? hw1 : hw0;
                float rs = 0.f;
                #pragma unroll
                for (int f = 0; f < 4; f++) {
                    const int n = pass * 128 + wn * 32 + f * 8 + tig * 2;
                    float x0 = fmaf(acc[ms][f][ch * 2 + 0], BSCALE_INV, hwrow[n]);
                    float x1 = fmaf(acc[ms][f][ch * 2 + 1], BSCALE_INV, hwrow[n + 1]);
                    rs += svp[n] * tanhf(x0) + svp[n + 1] * tanhf(x1);
                }
                rs += __shfl_xor_sync(0xffffffffu, rs, 1);
                rs += __shfl_xor_sync(0xffffffffu, rs, 2);
                if (tig == 0) atomicAdd(&rsm[r], rs);
            }
        }
    }

    __syncthreads();
    if (tid < TMM) atomicAdd(&g_logits[m0 + tid], rsm[tid]);
}

// ---------------------------------------------------------------------------
// softmax over S per batch. grid(64), block(256)
// ---------------------------------------------------------------------------
__global__ void softmax_kernel(float* __restrict__ out) {
    __shared__ float red[256];
    const int b = blockIdx.x;
    const int t = threadIdx.x;
    const float* row = g_logits + b * S_;
    float* orow = out + b * S_;

    float mx = -INFINITY;
    for (int i = t; i < S_; i += 256) mx = fmaxf(mx, row[i]);
    red[t] = mx;
    __syncthreads();
    for (int off = 128; off > 0; off >>= 1) {
        if (t < off) red[t] = fmaxf(red[t], red[t + off]);
        __syncthreads();
    }
    mx = red[0];
    __syncthreads();

    float sum = 0.f;
    for (int i = t; i < S_; i += 256) {
        float e = expf(row[i] - mx);
        orow[i] = e;
        sum += e;
    }
    red[t] = sum;
    __syncthreads();
    for (int off = 128; off > 0; off >>= 1) {
        if (t < off) red[t] += red[t + off];
        __syncthreads();
    }
    const float inv = 1.f / red[0];
    __syncthreads();
    for (int i = t; i < S_; i += 256) orow[i] *= inv;
}

// ---------------------------------------------------------------------------
extern "C" void kernel_launch(void* const* d_in, const int* in_sizes, int n_in,
                              void* d_out, int out_size) {
    const float* hidden = (const float*)d_in[0];   // [64, 512]
    const float* enc    = (const float*)d_in[1];   // [64, 1000, 1024]
    const float* attn_w = (const float*)d_in[2];   // [1536, 512]
    const float* attn_b = (const float*)d_in[3];   // [512]
    const float* v      = (const float*)d_in[4];   // [512]
    float* out = (float*)d_out;                    // [64, 1000]

    cudaFuncSetAttribute(gemm_kernel,
                         cudaFuncAttributeMaxDynamicSharedMemorySize, SM_TOTAL);

    prep_kernel<<<352, 512>>>(hidden, attn_w, attn_b);
    gemm_kernel<<<(M_ / TMM) * 2, NT, SM_TOTAL>>>(enc, v);
    softmax_kernel<<<B_, 256>>>(out);
}

// round 15
// speedup vs baseline: 1.3146x; 1.0137x over previous
#include <cuda_runtime.h>
#include <cuda_fp16.h>
#include <math.h>
#include <stdint.h>

// ---------------------------------------------------------------- constants
#define B_   64
#define S_   1000
#define D_   512          // N of the GEMM
#define K2_  1024         // K of the GEMM
#define M_   (B_ * S_)    // 64000

#define TMM  64           // CTA M tile (2 CTAs/SM)
#define KC   64           // K chunk (64 fp16 = 128B swizzled rows)
#define NCH  16           // K2_/KC
#define NT   256          // threads per CTA (8 warps = 2M x 4N)
#define PPC  2            // N-passes per CTA (split-N: 2 CTAs per m-tile)

#define BSCALE     256.0f       // B pre-scale (keeps Bl out of fp16 subnormals)
#define BSCALE_INV 0.00390625f  // 1/256

// ------------------------------------------------------------- device scratch
__device__ float g_hW[B_ * D_];
__device__ float g_logits[M_];
// W_bot*256 pre-split (hi/lo fp16), transposed [n][k], SW128-swizzled per chunk
__device__ __align__(16) uint8_t g_wprep_hi[NCH * D_ * 128];
__device__ __align__(16) uint8_t g_wprep_lo[NCH * D_ * 128];

// ---------------------------------------------------------------- smem layout
// A: [stage][64 rows][128B]          -> 2 x 8KB  = 16KB   (single fp16 plane)
// B: [stage][plane][128 rows][128B]  -> 4 x 16KB = 64KB
#define SA(st)      ((st) * 8192)
#define SB(st, pl)  (16384 + (st) * 32768 + (pl) * 16384)
#define SM_SV   81920       // 512 f32
#define SM_HW0  83968       // 512 f32
#define SM_HW1  86016       // 512 f32
#define SM_RS   88064       // 64 f32
#define SM_TOTAL 88320

// ---------------------------------------------------------------- helpers
__device__ __forceinline__ uint32_t smem_u32(const void* p) {
    uint32_t a;
    asm("{ .reg .u64 t; cvta.to.shared.u64 t, %1; cvt.u32.u64 %0, t; }" : "=r"(a) : "l"(p));
    return a;
}
__host__ __device__ __forceinline__ uint32_t swz128(uint32_t off) {
    return off ^ ((off >> 3) & 0x70);
}
#define LDSM4(R, A)                                                             \
    asm volatile("ldmatrix.sync.aligned.m8n8.x4.shared.b16 {%0,%1,%2,%3}, [%4];" \
        : "=r"((R)[0]), "=r"((R)[1]), "=r"((R)[2]), "=r"((R)[3]) : "r"(A))
// fp32-accumulator HMMA (precision-critical hi term)
__device__ __forceinline__ void mma_f16(float* c, const uint32_t* a, const uint32_t* b) {
    asm volatile("mma.sync.aligned.m16n8k16.row.col.f32.f16.f16.f32 "
        "{%0,%1,%2,%3},{%4,%5,%6,%7},{%8,%9},{%0,%1,%2,%3};"
        : "+f"(c[0]), "+f"(c[1]), "+f"(c[2]), "+f"(c[3])
        : "r"(a[0]), "r"(a[1]), "r"(a[2]), "r"(a[3]), "r"(b[0]), "r"(b[1]));
}
// fp16-accumulator HMMA (lo term: magnitude ~0.1, rounding negligible)
__device__ __forceinline__ void mma_f16acc(uint32_t* c, const uint32_t* a, const uint32_t* b) {
    asm volatile("mma.sync.aligned.m16n8k16.row.col.f16.f16.f16.f16 "
        "{%0,%1},{%2,%3,%4,%5},{%6,%7},{%0,%1};"
        : "+r"(c[0]), "+r"(c[1])
        : "r"(a[0]), "r"(a[1]), "r"(a[2]), "r"(a[3]), "r"(b[0]), "r"(b[1]));
}
#define CP16(dst, src) \
    asm volatile("cp.async.cg.shared.global [%0], [%1], 16;" :: "r"(dst), "l"(src) : "memory")
#define CP_COMMIT() asm volatile("cp.async.commit_group;" ::: "memory")
#define CP_WAIT0()  asm volatile("cp.async.wait_group 0;" ::: "memory")

// two fp32 -> packed fp16x2
__device__ __forceinline__ uint32_t pk2(float a, float b) {
    __half2 h = __halves2half2(__float2half(a), __float2half(b));
    return *reinterpret_cast<uint32_t*>(&h);
}

// ---------------------------------------------------------------------------
// FUSED prep kernel: hw [0,512) | conv_w [512,576) | zero logits [576,608)
// hw: 8 k-slices x 64 iters (short dependent chains).
// ---------------------------------------------------------------------------
__global__ __launch_bounds__(512)
void prep_kernel(const float* __restrict__ hidden,
                 const float* __restrict__ attn_w,
                 const float* __restrict__ attn_b) {
    const int bx = blockIdx.x;
    const int tid = threadIdx.x;

    if (bx < 512) {
        // ---- hW: 512 thr = 64 n-cols x 8 k-slices -----------------------
        __shared__ float sh[D_];
        __shared__ float part[7][64];
        const int b  = bx >> 3;
        const int ng = bx & 7;
        const int nl = tid & 63;
        const int ks = tid >> 6;                // 0..7
        const int n  = ng * 64 + nl;
        for (int i = tid; i < D_; i += 512) sh[i] = hidden[b * D_ + i];
        __syncthreads();
        const int k0 = ks * 64;
        float a0 = 0.f, a1 = 0.f, a2 = 0.f, a3 = 0.f;
        #pragma unroll 8
        for (int k = k0; k < k0 + 64; k += 4) {
            a0 += sh[k + 0] * attn_w[(k + 0) * D_ + n];
            a1 += sh[k + 1] * attn_w[(k + 1) * D_ + n];
            a2 += sh[k + 2] * attn_w[(k + 2) * D_ + n];
            a3 += sh[k + 3] * attn_w[(k + 3) * D_ + n];
        }
        float acc = (a0 + a1) + (a2 + a3);
        if (ks) part[ks - 1][nl] = acc;
        __syncthreads();
        if (ks == 0) {
            #pragma unroll
            for (int j = 0; j < 7; j++) acc += part[j][nl];
            g_hW[b * D_ + n] = attn_b[n] + acc;
        }
    } else if (bx < 576) {
        // ---- conv_w: W_bot*256 -> fp16 hi/lo, transpose + swizzle -------
        const int bi = bx - 512;
        const int chunk = bi >> 2;
        const int kg0 = (bi & 3) * 16;
        const int n = tid;
        uint8_t* dh = g_wprep_hi + chunk * (D_ * 128);
        uint8_t* dl = g_wprep_lo + chunk * (D_ * 128);
        for (int kk = kg0; kk < kg0 + 16; kk++) {
            const int kg = D_ + chunk * KC + kk;
            float w = attn_w[(size_t)kg * D_ + n] * BSCALE;
            __half hi = __float2half(w);
            __half lo = __float2half(w - __half2float(hi));
            uint32_t sw = swz128((uint32_t)(n * 128 + kk * 2));
            *reinterpret_cast<uint16_t*>(dh + sw) = *reinterpret_cast<uint16_t*>(&hi);
            *reinterpret_cast<uint16_t*>(dl + sw) = *reinterpret_cast<uint16_t*>(&lo);
        }
    } else {
        // ---- zero g_logits (split-N gemm accumulates via atomicAdd) -----
        const int bi = bx - 576;
        int idx = bi * 2048 + tid;
        #pragma unroll
        for (int j = 0; j < 4; j++) {
            if (idx < M_) g_logits[idx] = 0.f;
            idx += 512;
        }
    }
}

// ---------------------------------------------------------------------------
// Main HMMA GEMM + tanh + v-dot.  grid(2000), block(256), 2 CTAs/SM.
// fp16 2-term: A = fp16(enc) in-kernel; B = (W*256) fp16 hi+lo pre-swizzled.
// hi term -> fp32 accumulators; lo term -> fp16 accumulators (tiny magnitude).
// ---------------------------------------------------------------------------
__global__ __launch_bounds__(NT, 2)
void gemm_kernel(const float* __restrict__ enc, const float* __restrict__ v) {
    extern __shared__ __align__(1024) uint8_t smem[];
    const uint32_t sb = smem_u32(smem);
    const int tid  = threadIdx.x;
    const int wid  = tid >> 5;
    const int lane = tid & 31;
    const int wm   = wid >> 2;          // 0..1 (32 M rows each)
    const int wn   = wid & 3;           // 0..3 (32 N cols each)
    const int m0   = (blockIdx.x >> 1) * TMM;
    const int p0   = (blockIdx.x & 1) * PPC;   // first N-pass of this CTA

    float* svp = reinterpret_cast<float*>(smem + SM_SV);
    float* hw0 = reinterpret_cast<float*>(smem + SM_HW0);
    float* hw1 = reinterpret_cast<float*>(smem + SM_HW1);
    float* rsm = reinterpret_cast<float*>(smem + SM_RS);

    // ---- A conversion mapping: thread -> (row, 16-float k-group) ----------
    const int arow = tid >> 2;              // 0..63
    const int ak16 = tid & 3;               // 16-float group within chunk
    const float* abase = enc + (size_t)(m0 + arow) * K2_ + ak16 * 16;
    const uint32_t adst0 = (uint32_t)arow * 128 +
                           (((uint32_t)(ak16 * 2 + 0) << 4) ^ ((uint32_t)(arow & 7) << 4));
    const uint32_t adst1 = (uint32_t)arow * 128 +
                           (((uint32_t)(ak16 * 2 + 1) << 4) ^ ((uint32_t)(arow & 7) << 4));

    // ---- B cp.async loader (pre-swizzled images: straight copy) -----------
    auto loadB = [&](int pass, int chunk, int st) {
        const uint8_t* gh = g_wprep_hi + chunk * (D_ * 128) + pass * (128 * 128);
        const uint8_t* gl = g_wprep_lo + chunk * (D_ * 128) + pass * (128 * 128);
        #pragma unroll
        for (int j = 0; j < 4; j++) {
            uint32_t idx = (uint32_t)(tid + j * NT) * 16;
            CP16(sb + SB(st, 0) + idx, gh + idx);
            CP16(sb + SB(st, 1) + idx, gl + idx);
        }
        CP_COMMIT();
    };
    // A: 16 fp32 -> 16 fp16 (single plane), two swizzled 16B stores
    auto stA = [&](const float4& f0, const float4& f1,
                   const float4& f2, const float4& f3, int st) {
        uint4 p0v, p1v;
        p0v.x = pk2(f0.x, f0.y);
        p0v.y = pk2(f0.z, f0.w);
        p0v.z = pk2(f1.x, f1.y);
        p0v.w = pk2(f1.z, f1.w);
        p1v.x = pk2(f2.x, f2.y);
        p1v.y = pk2(f2.z, f2.w);
        p1v.z = pk2(f3.x, f3.y);
        p1v.w = pk2(f3.z, f3.w);
        *reinterpret_cast<uint4*>(smem + SA(st) + adst0) = p0v;
        *reinterpret_cast<uint4*>(smem + SA(st) + adst1) = p1v;
    };

    // ---- per-lane ldmatrix address components ------------------------------
    const int a_r16 = lane & 15;
    const uint32_t a_kext = (lane >> 4) << 4;
    uint32_t aoff[2], aswz[2];
    #pragma unroll
    for (int ms = 0; ms < 2; ms++) {
        int r = wm * 32 + ms * 16 + a_r16;
        aoff[ms] = (uint32_t)r * 128;
        aswz[ms] = (uint32_t)(r & 7) << 4;
    }
    const int b_r16 = (lane & 7) | ((lane & 16) >> 1);
    const uint32_t b_kext = (lane & 8) << 1;
    uint32_t boff[2], bsw[2];
    #pragma unroll
    for (int np = 0; np < 2; np++) {
        int r = wn * 32 + np * 16 + b_r16;
        boff[np] = (uint32_t)r * 128;
        bsw[np]  = (uint32_t)(r & 7) << 4;
    }

    // ---- CTA prologue: chunk 0 of pass p0 ----------------------------------
    {
        const float* ap = abase;   // chunk 0
        float4 f0 = reinterpret_cast<const float4*>(ap)[0];
        float4 f1 = reinterpret_cast<const float4*>(ap)[1];
        float4 f2 = reinterpret_cast<const float4*>(ap)[2];
        float4 f3 = reinterpret_cast<const float4*>(ap)[3];
        loadB(p0, 0, 0);
        const int b0i = m0 / S_;
        const int b1i = (m0 + TMM - 1) / S_;
        for (int i = tid; i < D_; i += NT) {
            svp[i] = v[i];
            hw0[i] = g_hW[b0i * D_ + i];
            hw1[i] = g_hW[b1i * D_ + i];
        }
        if (tid < TMM) rsm[tid] = 0.f;
        stA(f0, f1, f2, f3, 0);
    }
    const int b0 = m0 / S_;
    const int thr = (b0 + 1) * S_ - m0;   // rows >= thr belong to batch b0+1

    float    acc[2][4][4];     // hi term, fp32
    uint32_t accl[2][4][2];    // lo term, packed fp16 pairs

    auto compute = [&](int st) {
        const uint32_t baseA  = sb + SA(st);
        const uint32_t baseBh = sb + SB(st, 0);
        const uint32_t baseBl = sb + SB(st, 1);
        #pragma unroll
        for (int k16 = 0; k16 < 4; k16++) {
            const uint32_t ka = (uint32_t)(k16 * 32) + a_kext;
            const uint32_t kb = (uint32_t)(k16 * 32) + b_kext;
            uint32_t ah[2][4];
            #pragma unroll
            for (int ms = 0; ms < 2; ms++)
                LDSM4(ah[ms], baseA + aoff[ms] + (ka ^ aswz[ms]));
            #pragma unroll
            for (int np = 0; np < 2; np++) {
                const uint32_t o = boff[np] + (kb ^ bsw[np]);
                uint32_t bh[4], bl[4];
                LDSM4(bh, baseBh + o);
                LDSM4(bl, baseBl + o);
                #pragma unroll
                for (int ms = 0; ms < 2; ms++) {
                    mma_f16(acc[ms][np * 2 + 0], ah[ms], bh + 0);
                    mma_f16(acc[ms][np * 2 + 1], ah[ms], bh + 2);
                    mma_f16acc(accl[ms][np * 2 + 0], ah[ms], bl + 0);
                    mma_f16acc(accl[ms][np * 2 + 1], ah[ms], bl + 2);
                }
            }
        }
    };

    const int gid = lane >> 2;
    const int tig = lane & 3;

    // ======================= PPC N-passes (128 cols each) ===================
    #pragma unroll 1
    for (int pi = 0; pi < PPC; pi++) {
        const int pass = p0 + pi;
        #pragma unroll
        for (int ms = 0; ms < 2; ms++)
            #pragma unroll
            for (int f = 0; f < 4; f++) {
                #pragma unroll
                for (int c = 0; c < 4; c++) acc[ms][f][c] = 0.f;
                accl[ms][f][0] = 0u;
                accl[ms][f][1] = 0u;
            }

        // ONE sync per chunk; next chunk's A LDG issued before compute
        // (latency hidden), converted+stored after compute into the freed stage.
        #pragma unroll 1
        for (int i = 0; i < NCH; i++) {
            const int s = i & 1;
            CP_WAIT0();
            __syncthreads();
            int nchunk = -1, npass = pass, nst = s ^ 1;
            if (i + 1 < NCH)       { nchunk = i + 1; }
            else if (pi + 1 < PPC) { nchunk = 0; npass = pass + 1; nst = 0; }
            float4 f0, f1, f2, f3;
            if (nchunk >= 0) {
                const float* ap = abase + nchunk * KC;
                f0 = reinterpret_cast<const float4*>(ap)[0];
                f1 = reinterpret_cast<const float4*>(ap)[1];
                f2 = reinterpret_cast<const float4*>(ap)[2];
                f3 = reinterpret_cast<const float4*>(ap)[3];
                loadB(npass, nchunk, nst);
            }
            compute(s);
            if (nchunk >= 0) stA(f0, f1, f2, f3, nst);
        }

        // epilogue: x = (acc_hi + acc_lo)/256 + hW, rowsum += v * tanh(x)
        #pragma unroll
        for (int ms = 0; ms < 2; ms++) {
            #pragma unroll
            for (int ch = 0; ch < 2; ch++) {
                const int r = wm * 32 + ms * 16 + ch * 8 + gid;
                const float* hwrow = (r >= thr) ? hw1 : hw0;
                float rs = 0.f;
                #pragma unroll
                for (int f = 0; f < 4; f++) {
                    const int n = pass * 128 + wn * 32 + f * 8 + tig * 2;
                    __half2 lop = *reinterpret_cast<__half2*>(&accl[ms][f][ch]);
                    float x0 = fmaf(acc[ms][f][ch * 2 + 0] + __low2float(lop),
                                    BSCALE_INV, hwrow[n]);
                    float x1 = fmaf(acc[ms][f][ch * 2 + 1] + __high2float(lop),
                                    BSCALE_INV, hwrow[n + 1]);
                    rs += svp[n] * tanhf(x0) + svp[n + 1] * tanhf(x1);
                }
                rs += __shfl_xor_sync(0xffffffffu, rs, 1);
                rs += __shfl_xor_sync(0xffffffffu, rs, 2);
                if (tig == 0) atomicAdd(&rsm[r], rs);
            }
        }
    }

    __syncthreads();
    if (tid < TMM) atomicAdd(&g_logits[m0 + tid], rsm[tid]);
}

// ---------------------------------------------------------------------------
// softmax over S per batch. grid(64), block(256)
// ---------------------------------------------------------------------------
__global__ void softmax_kernel(float* __restrict__ out) {
    __shared__ float red[256];
    const int b = blockIdx.x;
    const int t = threadIdx.x;
    const float* row = g_logits + b * S_;
    float* orow = out + b * S_;

    float mx = -INFINITY;
    for (int i = t; i < S_; i += 256) mx = fmaxf(mx, row[i]);
    red[t] = mx;
    __syncthreads();
    for (int off = 128; off > 0; off >>= 1) {
        if (t < off) red[t] = fmaxf(red[t], red[t + off]);
        __syncthreads();
    }
    mx = red[0];
    __syncthreads();

    float sum = 0.f;
    for (int i = t; i < S_; i += 256) {
        float e = expf(row[i] - mx);
        orow[i] = e;
        sum += e;
    }
    red[t] = sum;
    __syncthreads();
    for (int off = 128; off > 0; off >>= 1) {
        if (t < off) red[t] += red[t + off];
        __syncthreads();
    }
    const float inv = 1.f / red[0];
    __syncthreads();
    for (int i = t; i < S_; i += 256) orow[i] *= inv;
}

// ---------------------------------------------------------------------------
extern "C" void kernel_launch(void* const* d_in, const int* in_sizes, int n_in,
                              void* d_out, int out_size) {
    const float* hidden = (const float*)d_in[0];   // [64, 512]
    const float* enc    = (const float*)d_in[1];   // [64, 1000, 1024]
    const float* attn_w = (const float*)d_in[2];   // [1536, 512]
    const float* attn_b = (const float*)d_in[3];   // [512]
    const float* v      = (const float*)d_in[4];   // [512]
    float* out = (float*)d_out;                    // [64, 1000]

    cudaFuncSetAttribute(gemm_kernel,
                         cudaFuncAttributeMaxDynamicSharedMemorySize, SM_TOTAL);

    prep_kernel<<<608, 512>>>(hidden, attn_w, attn_b);
    gemm_kernel<<<(M_ / TMM) * 2, NT, SM_TOTAL>>>(enc, v);
    softmax_kernel<<<B_, 256>>>(out);
}

// round 16
// speedup vs baseline: 1.3506x; 1.0274x over previous
#include <cuda_runtime.h>
#include <cuda_fp16.h>
#include <math.h>
#include <stdint.h>

// ---------------------------------------------------------------- constants
#define B_   64
#define S_   1000
#define D_   512          // N of the GEMM
#define K2_  1024         // K of the GEMM
#define M_   (B_ * S_)    // 64000

#define TMM  64           // CTA M tile (2 CTAs/SM)
#define KC   64           // K chunk (64 fp16 = 128B swizzled rows)
#define NCH  16           // K2_/KC
#define NT   256          // threads per CTA (8 warps = 2M x 4N)
#define PPC  2            // N-passes per CTA (split-N: 2 CTAs per m-tile)

#define BSCALE     256.0f       // B pre-scale (keeps Bl out of fp16 subnormals)
#define BSCALE_INV 0.00390625f  // 1/256

// ------------------------------------------------------------- device scratch
__device__ float g_hW[B_ * D_];
__device__ float g_logits[M_];
// W_bot*256 pre-split (hi/lo fp16), transposed [n][k], SW128-swizzled per chunk
__device__ __align__(16) uint8_t g_wprep_hi[NCH * D_ * 128];
__device__ __align__(16) uint8_t g_wprep_lo[NCH * D_ * 128];

// ---------------------------------------------------------------- smem layout
// A: [stage][64 rows][128B]          -> 2 x 8KB  = 16KB   (single fp16 plane)
// B: [stage][plane][128 rows][128B]  -> 4 x 16KB = 64KB
#define SA(st)      ((st) * 8192)
#define SB(st, pl)  (16384 + (st) * 32768 + (pl) * 16384)
#define SM_SV   81920       // 512 f32
#define SM_HW0  83968       // 512 f32
#define SM_HW1  86016       // 512 f32
#define SM_RS   88064       // 64 f32
#define SM_TOTAL 88320

// ---------------------------------------------------------------- helpers
__device__ __forceinline__ uint32_t smem_u32(const void* p) {
    uint32_t a;
    asm("{ .reg .u64 t; cvta.to.shared.u64 t, %1; cvt.u32.u64 %0, t; }" : "=r"(a) : "l"(p));
    return a;
}
__host__ __device__ __forceinline__ uint32_t swz128(uint32_t off) {
    return off ^ ((off >> 3) & 0x70);
}
#define LDSM4(R, A)                                                             \
    asm volatile("ldmatrix.sync.aligned.m8n8.x4.shared.b16 {%0,%1,%2,%3}, [%4];" \
        : "=r"((R)[0]), "=r"((R)[1]), "=r"((R)[2]), "=r"((R)[3]) : "r"(A))
// fp32-accumulator HMMA (precision-critical hi term)
__device__ __forceinline__ void mma_f16(float* c, const uint32_t* a, const uint32_t* b) {
    asm volatile("mma.sync.aligned.m16n8k16.row.col.f32.f16.f16.f32 "
        "{%0,%1,%2,%3},{%4,%5,%6,%7},{%8,%9},{%0,%1,%2,%3};"
        : "+f"(c[0]), "+f"(c[1]), "+f"(c[2]), "+f"(c[3])
        : "r"(a[0]), "r"(a[1]), "r"(a[2]), "r"(a[3]), "r"(b[0]), "r"(b[1]));
}
// fp16-accumulator HMMA (lo term: magnitude ~0.1, rounding negligible;
// same issue rate as F32-acc on sm_103 but saves 2 regs per fragment)
__device__ __forceinline__ void mma_f16acc(uint32_t* c, const uint32_t* a, const uint32_t* b) {
    asm volatile("mma.sync.aligned.m16n8k16.row.col.f16.f16.f16.f16 "
        "{%0,%1},{%2,%3,%4,%5},{%6,%7},{%0,%1};"
        : "+r"(c[0]), "+r"(c[1])
        : "r"(a[0]), "r"(a[1]), "r"(a[2]), "r"(a[3]), "r"(b[0]), "r"(b[1]));
}
#define CP16(dst, src) \
    asm volatile("cp.async.cg.shared.global [%0], [%1], 16;" :: "r"(dst), "l"(src) : "memory")
#define CP_COMMIT() asm volatile("cp.async.commit_group;" ::: "memory")
#define CP_WAIT0()  asm volatile("cp.async.wait_group 0;" ::: "memory")

// two fp32 -> packed fp16x2
__device__ __forceinline__ uint32_t pk2(float a, float b) {
    __half2 h = __halves2half2(__float2half(a), __float2half(b));
    return *reinterpret_cast<uint32_t*>(&h);
}

// ---------------------------------------------------------------------------
// FUSED prep kernel: hw [0,512) | conv_w [512,640) | zero logits [640,672)
// hw: 8 k-slices x 8 independent accumulators (MLP=8).
// conv_w: kk paired -> 4-byte stores (kk, kk+1 share a word post-swizzle).
// ---------------------------------------------------------------------------
__global__ __launch_bounds__(512)
void prep_kernel(const float* __restrict__ hidden,
                 const float* __restrict__ attn_w,
                 const float* __restrict__ attn_b) {
    const int bx = blockIdx.x;
    const int tid = threadIdx.x;

    if (bx < 512) {
        // ---- hW: 512 thr = 64 n-cols x 8 k-slices, 8-wide ILP ------------
        __shared__ float sh[D_];
        __shared__ float part[7][64];
        const int b  = bx >> 3;
        const int ng = bx & 7;
        const int nl = tid & 63;
        const int ks = tid >> 6;                // 0..7
        const int n  = ng * 64 + nl;
        for (int i = tid; i < D_; i += 512) sh[i] = hidden[b * D_ + i];
        __syncthreads();
        const int k0 = ks * 64;
        float a[8];
        #pragma unroll
        for (int j = 0; j < 8; j++) a[j] = 0.f;
        #pragma unroll 4
        for (int k = k0; k < k0 + 64; k += 8) {
            #pragma unroll
            for (int j = 0; j < 8; j++)
                a[j] += sh[k + j] * attn_w[(k + j) * D_ + n];
        }
        float acc = ((a[0] + a[1]) + (a[2] + a[3])) + ((a[4] + a[5]) + (a[6] + a[7]));
        if (ks) part[ks - 1][nl] = acc;
        __syncthreads();
        if (ks == 0) {
            #pragma unroll
            for (int j = 0; j < 7; j++) acc += part[j][nl];
            g_hW[b * D_ + n] = attn_b[n] + acc;
        }
    } else if (bx < 640) {
        // ---- conv_w: W_bot*256 -> fp16 hi/lo, transpose + swizzle --------
        // kk processed in pairs: (kk,kk+1) land in one 4B word after swizzle.
        const int bi = bx - 512;               // 0..127
        const int chunk = bi >> 3;             // 16 chunks
        const int kg0 = (bi & 7) * 8;          // 8 kk per block
        const int n = tid;
        uint8_t* dh = g_wprep_hi + chunk * (D_ * 128);
        uint8_t* dl = g_wprep_lo + chunk * (D_ * 128);
        #pragma unroll
        for (int kk = kg0; kk < kg0 + 8; kk += 2) {
            const int kg = D_ + chunk * KC + kk;
            float w0 = attn_w[(size_t)(kg + 0) * D_ + n] * BSCALE;
            float w1 = attn_w[(size_t)(kg + 1) * D_ + n] * BSCALE;
            __half h0 = __float2half(w0);
            __half h1 = __float2half(w1);
            __half l0 = __float2half(w0 - __half2float(h0));
            __half l1 = __float2half(w1 - __half2float(h1));
            __half2 hp = __halves2half2(h0, h1);
            __half2 lp = __halves2half2(l0, l1);
            uint32_t sw = swz128((uint32_t)(n * 128 + kk * 2));
            *reinterpret_cast<uint32_t*>(dh + sw) = *reinterpret_cast<uint32_t*>(&hp);
            *reinterpret_cast<uint32_t*>(dl + sw) = *reinterpret_cast<uint32_t*>(&lp);
        }
    } else {
        // ---- zero g_logits (split-N gemm accumulates via atomicAdd) -----
        const int bi = bx - 640;
        int idx = bi * 2048 + tid;
        #pragma unroll
        for (int j = 0; j < 4; j++) {
            if (idx < M_) g_logits[idx] = 0.f;
            idx += 512;
        }
    }
}

// ---------------------------------------------------------------------------
// Main HMMA GEMM + tanh + v-dot.  grid(2000), block(256), 2 CTAs/SM.
// fp16 2-term: A = fp16(enc) in-kernel; B = (W*256) fp16 hi+lo pre-swizzled.
// hi term -> fp32 accumulators; lo term -> fp16 accumulators.
// UNCHANGED from round 15 (at the HMMA issue floor).
// ---------------------------------------------------------------------------
__global__ __launch_bounds__(NT, 2)
void gemm_kernel(const float* __restrict__ enc, const float* __restrict__ v) {
    extern __shared__ __align__(1024) uint8_t smem[];
    const uint32_t sb = smem_u32(smem);
    const int tid  = threadIdx.x;
    const int wid  = tid >> 5;
    const int lane = tid & 31;
    const int wm   = wid >> 2;          // 0..1 (32 M rows each)
    const int wn   = wid & 3;           // 0..3 (32 N cols each)
    const int m0   = (blockIdx.x >> 1) * TMM;
    const int p0   = (blockIdx.x & 1) * PPC;   // first N-pass of this CTA

    float* svp = reinterpret_cast<float*>(smem + SM_SV);
    float* hw0 = reinterpret_cast<float*>(smem + SM_HW0);
    float* hw1 = reinterpret_cast<float*>(smem + SM_HW1);
    float* rsm = reinterpret_cast<float*>(smem + SM_RS);

    // ---- A conversion mapping: thread -> (row, 16-float k-group) ----------
    const int arow = tid >> 2;              // 0..63
    const int ak16 = tid & 3;               // 16-float group within chunk
    const float* abase = enc + (size_t)(m0 + arow) * K2_ + ak16 * 16;
    const uint32_t adst0 = (uint32_t)arow * 128 +
                           (((uint32_t)(ak16 * 2 + 0) << 4) ^ ((uint32_t)(arow & 7) << 4));
    const uint32_t adst1 = (uint32_t)arow * 128 +
                           (((uint32_t)(ak16 * 2 + 1) << 4) ^ ((uint32_t)(arow & 7) << 4));

    // ---- B cp.async loader (pre-swizzled images: straight copy) -----------
    auto loadB = [&](int pass, int chunk, int st) {
        const uint8_t* gh = g_wprep_hi + chunk * (D_ * 128) + pass * (128 * 128);
        const uint8_t* gl = g_wprep_lo + chunk * (D_ * 128) + pass * (128 * 128);
        #pragma unroll
        for (int j = 0; j < 4; j++) {
            uint32_t idx = (uint32_t)(tid + j * NT) * 16;
            CP16(sb + SB(st, 0) + idx, gh + idx);
            CP16(sb + SB(st, 1) + idx, gl + idx);
        }
        CP_COMMIT();
    };
    // A: 16 fp32 -> 16 fp16 (single plane), two swizzled 16B stores
    auto stA = [&](const float4& f0, const float4& f1,
                   const float4& f2, const float4& f3, int st) {
        uint4 p0v, p1v;
        p0v.x = pk2(f0.x, f0.y);
        p0v.y = pk2(f0.z, f0.w);
        p0v.z = pk2(f1.x, f1.y);
        p0v.w = pk2(f1.z, f1.w);
        p1v.x = pk2(f2.x, f2.y);
        p1v.y = pk2(f2.z, f2.w);
        p1v.z = pk2(f3.x, f3.y);
        p1v.w = pk2(f3.z, f3.w);
        *reinterpret_cast<uint4*>(smem + SA(st) + adst0) = p0v;
        *reinterpret_cast<uint4*>(smem + SA(st) + adst1) = p1v;
    };

    // ---- per-lane ldmatrix address components ------------------------------
    const int a_r16 = lane & 15;
    const uint32_t a_kext = (lane >> 4) << 4;
    uint32_t aoff[2], aswz[2];
    #pragma unroll
    for (int ms = 0; ms < 2; ms++) {
        int r = wm * 32 + ms * 16 + a_r16;
        aoff[ms] = (uint32_t)r * 128;
        aswz[ms] = (uint32_t)(r & 7) << 4;
    }
    const int b_r16 = (lane & 7) | ((lane & 16) >> 1);
    const uint32_t b_kext = (lane & 8) << 1;
    uint32_t boff[2], bsw[2];
    #pragma unroll
    for (int np = 0; np < 2; np++) {
        int r = wn * 32 + np * 16 + b_r16;
        boff[np] = (uint32_t)r * 128;
        bsw[np]  = (uint32_t)(r & 7) << 4;
    }

    // ---- CTA prologue: chunk 0 of pass p0 ----------------------------------
    {
        const float* ap = abase;   // chunk 0
        float4 f0 = reinterpret_cast<const float4*>(ap)[0];
        float4 f1 = reinterpret_cast<const float4*>(ap)[1];
        float4 f2 = reinterpret_cast<const float4*>(ap)[2];
        float4 f3 = reinterpret_cast<const float4*>(ap)[3];
        loadB(p0, 0, 0);
        const int b0i = m0 / S_;
        const int b1i = (m0 + TMM - 1) / S_;
        for (int i = tid; i < D_; i += NT) {
            svp[i] = v[i];
            hw0[i] = g_hW[b0i * D_ + i];
            hw1[i] = g_hW[b1i * D_ + i];
        }
        if (tid < TMM) rsm[tid] = 0.f;
        stA(f0, f1, f2, f3, 0);
    }
    const int b0 = m0 / S_;
    const int thr = (b0 + 1) * S_ - m0;   // rows >= thr belong to batch b0+1

    float    acc[2][4][4];     // hi term, fp32
    uint32_t accl[2][4][2];    // lo term, packed fp16 pairs

    auto compute = [&](int st) {
        const uint32_t baseA  = sb + SA(st);
        const uint32_t baseBh = sb + SB(st, 0);
        const uint32_t baseBl = sb + SB(st, 1);
        #pragma unroll
        for (int k16 = 0; k16 < 4; k16++) {
            const uint32_t ka = (uint32_t)(k16 * 32) + a_kext;
            const uint32_t kb = (uint32_t)(k16 * 32) + b_kext;
            uint32_t ah[2][4];
            #pragma unroll
            for (int ms = 0; ms < 2; ms++)
                LDSM4(ah[ms], baseA + aoff[ms] + (ka ^ aswz[ms]));
            #pragma unroll
            for (int np = 0; np < 2; np++) {
                const uint32_t o = boff[np] + (kb ^ bsw[np]);
                uint32_t bh[4], bl[4];
                LDSM4(bh, baseBh + o);
                LDSM4(bl, baseBl + o);
                #pragma unroll
                for (int ms = 0; ms < 2; ms++) {
                    mma_f16(acc[ms][np * 2 + 0], ah[ms], bh + 0);
                    mma_f16(acc[ms][np * 2 + 1], ah[ms], bh + 2);
                    mma_f16acc(accl[ms][np * 2 + 0], ah[ms], bl + 0);
                    mma_f16acc(accl[ms][np * 2 + 1], ah[ms], bl + 2);
                }
            }
        }
    };

    const int gid = lane >> 2;
    const int tig = lane & 3;

    // ======================= PPC N-passes (128 cols each) ===================
    #pragma unroll 1
    for (int pi = 0; pi < PPC; pi++) {
        const int pass = p0 + pi;
        #pragma unroll
        for (int ms = 0; ms < 2; ms++)
            #pragma unroll
            for (int f = 0; f < 4; f++) {
                #pragma unroll
                for (int c = 0; c < 4; c++) acc[ms][f][c] = 0.f;
                accl[ms][f][0] = 0u;
                accl[ms][f][1] = 0u;
            }

        // ONE sync per chunk; next chunk's A LDG issued before compute
        // (latency hidden), converted+stored after compute into the freed stage.
        #pragma unroll 1
        for (int i = 0; i < NCH; i++) {
            const int s = i & 1;
            CP_WAIT0();
            __syncthreads();
            int nchunk = -1, npass = pass, nst = s ^ 1;
            if (i + 1 < NCH)       { nchunk = i + 1; }
            else if (pi + 1 < PPC) { nchunk = 0; npass = pass + 1; nst = 0; }
            float4 f0, f1, f2, f3;
            if (nchunk >= 0) {
                const float* ap = abase + nchunk * KC;
                f0 = reinterpret_cast<const float4*>(ap)[0];
                f1 = reinterpret_cast<const float4*>(ap)[1];
                f2 = reinterpret_cast<const float4*>(ap)[2];
                f3 = reinterpret_cast<const float4*>(ap)[3];
                loadB(npass, nchunk, nst);
            }
            compute(s);
            if (nchunk >= 0) stA(f0, f1, f2, f3, nst);
        }

        // epilogue: x = (acc_hi + acc_lo)/256 + hW, rowsum += v * tanh(x)
        #pragma unroll
        for (int ms = 0; ms < 2; ms++) {
            #pragma unroll
            for (int ch = 0; ch < 2; ch++) {
                const int r = wm * 32 + ms * 16 + ch * 8 + gid;
                const float* hwrow = (r >= thr) ? hw1 : hw0;
                float rs = 0.f;
                #pragma unroll
                for (int f = 0; f < 4; f++) {
                    const int n = pass * 128 + wn * 32 + f * 8 + tig * 2;
                    __half2 lop = *reinterpret_cast<__half2*>(&accl[ms][f][ch]);
                    float x0 = fmaf(acc[ms][f][ch * 2 + 0] + __low2float(lop),
                                    BSCALE_INV, hwrow[n]);
                    float x1 = fmaf(acc[ms][f][ch * 2 + 1] + __high2float(lop),
                                    BSCALE_INV, hwrow[n + 1]);
                    rs += svp[n] * tanhf(x0) + svp[n + 1] * tanhf(x1);
                }
                rs += __shfl_xor_sync(0xffffffffu, rs, 1);
                rs += __shfl_xor_sync(0xffffffffu, rs, 2);
                if (tig == 0) atomicAdd(&rsm[r], rs);
            }
        }
    }

    __syncthreads();
    if (tid < TMM) atomicAdd(&g_logits[m0 + tid], rsm[tid]);
}

// ---------------------------------------------------------------------------
// softmax over S per batch. grid(64), block(256)
// ---------------------------------------------------------------------------
__global__ void softmax_kernel(float* __restrict__ out) {
    __shared__ float red[256];
    const int b = blockIdx.x;
    const int t = threadIdx.x;
    const float* row = g_logits + b * S_;
    float* orow = out + b * S_;

    float mx = -INFINITY;
    for (int i = t; i < S_; i += 256) mx = fmaxf(mx, row[i]);
    red[t] = mx;
    __syncthreads();
    for (int off = 128; off > 0; off >>= 1) {
        if (t < off) red[t] = fmaxf(red[t], red[t + off]);
        __syncthreads();
    }
    mx = red[0];
    __syncthreads();

    float sum = 0.f;
    for (int i = t; i < S_; i += 256) {
        float e = expf(row[i] - mx);
        orow[i] = e;
        sum += e;
    }
    red[t] = sum;
    __syncthreads();
    for (int off = 128; off > 0; off >>= 1) {
        if (t < off) red[t] += red[t + off];
        __syncthreads();
    }
    const float inv = 1.f / red[0];
    __syncthreads();
    for (int i = t; i < S_; i += 256) orow[i] *= inv;
}

// ---------------------------------------------------------------------------
extern "C" void kernel_launch(void* const* d_in, const int* in_sizes, int n_in,
                              void* d_out, int out_size) {
    const float* hidden = (const float*)d_in[0];   // [64, 512]
    const float* enc    = (const float*)d_in[1];   // [64, 1000, 1024]
    const float* attn_w = (const float*)d_in[2];   // [1536, 512]
    const float* attn_b = (const float*)d_in[3];   // [512]
    const float* v      = (const float*)d_in[4];   // [512]
    float* out = (float*)d_out;                    // [64, 1000]

    cudaFuncSetAttribute(gemm_kernel,
                         cudaFuncAttributeMaxDynamicSharedMemorySize, SM_TOTAL);

    prep_kernel<<<672, 512>>>(hidden, attn_w, attn_b);
    gemm_kernel<<<(M_ / TMM) * 2, NT, SM_TOTAL>>>(enc, v);
    softmax_kernel<<<B_, 256>>>(out);
}